// round 1
// baseline (speedup 1.0000x reference)
#include <cuda_runtime.h>
#include <math.h>

#define BB   32
#define HH   40
#define WW   256
#define FREQ 40
#define C0   32
#define H0   38
#define W0   254
#define C1   64
#define H1   36
#define W1   252
#define K_FC (C1*H1*W1)      /* 580608 */
#define KC   2304
#define NCHUNK 252           /* K_FC / KC */
#define KT   64
#define TWO_PI 6.28318530717958647692f

/* ---------------- scratch (device globals: no allocation allowed) -------- */
__device__ float g_x0[BB*C0*H0*W0];          /* conv0 output, ~39.5 MB */
__device__ float g_x1[(size_t)BB*K_FC];      /* conv1 output [b][k], ~74 MB */
__device__ float g_feats[BB*HH*WW];
__device__ float g_sin[FREQ*WW];
__device__ float g_cos[FREQ*WW];
__device__ float g_gpart[NCHUNK*FREQ*BB];
__device__ float g_gates[BB*FREQ];

/* ---------------- conv0: 1->32ch 3x3 VALID + bias + relu ----------------- */
__global__ void conv0_kernel(const float* __restrict__ in,
                             const float* __restrict__ w0,
                             const float* __restrict__ b0) {
    int idx = blockIdx.x*blockDim.x + threadIdx.x;
    int jg = idx & 63;          /* 64 groups of 4 cols cover 254 */
    int t  = idx >> 6;
    int i  = t % H0; t /= H0;
    int oc = t % C0; t /= C0;
    int b  = t;
    if (b >= BB) return;
    int j0 = jg*4;

    float w[9];
#pragma unroll
    for (int q = 0; q < 9; q++) w[q] = __ldg(&w0[oc*9+q]);

    float bias = __ldg(&b0[oc]);
    float acc0 = bias, acc1 = bias, acc2 = bias, acc3 = bias;

    const float* ip = in + (size_t)b*HH*WW;
#pragma unroll
    for (int di = 0; di < 3; di++) {
        const float* row = ip + (i+di)*WW;
        float x[6];
#pragma unroll
        for (int c = 0; c < 6; c++) x[c] = (j0+c < WW) ? row[j0+c] : 0.0f;
#pragma unroll
        for (int dj = 0; dj < 3; dj++) {
            float wv = w[di*3+dj];
            acc0 += wv * x[0+dj];
            acc1 += wv * x[1+dj];
            acc2 += wv * x[2+dj];
            acc3 += wv * x[3+dj];
        }
    }
    float* op = g_x0 + (((size_t)b*C0 + oc)*H0 + i)*W0 + j0;
    if (j0+0 < W0) op[0] = fmaxf(acc0, 0.0f);
    if (j0+1 < W0) op[1] = fmaxf(acc1, 0.0f);
    if (j0+2 < W0) op[2] = fmaxf(acc2, 0.0f);
    if (j0+3 < W0) op[3] = fmaxf(acc3, 0.0f);
}

/* ---------------- feats: 5-tap conv along W, zero pad, + bias ------------ */
__global__ void feats_kernel(const float* __restrict__ in,
                             const float* __restrict__ wf,
                             const float* __restrict__ bf) {
    int idx = blockIdx.x*blockDim.x + threadIdx.x;
    if (idx >= BB*HH*WW) return;
    int w = idx & (WW-1);
    const float* row = in + (idx - w);   /* (b*H+h)*W base */
    float acc = __ldg(&bf[0]);
#pragma unroll
    for (int t = 0; t < 5; t++) {
        int ww = w + t - 2;
        if (ww >= 0 && ww < WW) acc += __ldg(&wf[t]) * row[ww];
    }
    g_feats[idx] = acc;
}

/* ---------------- sin/cos phase tables ----------------------------------- */
__global__ void trig_kernel() {
    int f = blockIdx.x;
    int w = threadIdx.x;
    float fs = 2.0f * (float)(f+1);
    float t  = (0.5f/255.0f) * (float)w;
    float ph = TWO_PI * fs * t;
    g_sin[f*WW + w] = sinf(ph);
    g_cos[f*WW + w] = cosf(ph);
}

/* ---------------- conv1: 32->64ch 3x3 VALID + bias + relu ----------------
 * grid (36 rows, 32 batch, 2 oc-halves), 512 threads.
 * smem: w1 slice [288][32] + x0 slab [32][3][256].
 * Each active thread: 4 oc x 4 j register tile -> 48 FMA per (ic,di) step. */
__global__ void conv1_kernel(const float* __restrict__ w1,
                             const float* __restrict__ b1) {
    extern __shared__ float sm[];
    float* w1s = sm;                 /* 288*32 = 9216 floats  */
    float* x0s = sm + 288*32;        /* 32*3*256 = 24576 floats */

    int i    = blockIdx.x;
    int b    = blockIdx.y;
    int half = blockIdx.z;
    int tid  = threadIdx.x;

    for (int t = tid; t < 288*32; t += 512) {
        int kk  = t >> 5;
        int ocl = t & 31;
        w1s[t] = w1[(half*32 + ocl)*288 + kk];
    }
    for (int t = tid; t < 32*3*254; t += 512) {
        int col = t % 254;
        int r   = t / 254;
        int di  = r % 3;
        int ic  = r / 3;
        x0s[(ic*3 + di)*256 + col] =
            g_x0[(((size_t)b*C0 + ic)*H0 + (i+di))*W0 + col];
    }
    __syncthreads();

    int jg = tid % 63;
    int og = tid / 63;
    if (og >= 8) return;
    int j0 = jg*4;

    float acc[4][4];
#pragma unroll
    for (int o = 0; o < 4; o++)
#pragma unroll
        for (int jj = 0; jj < 4; jj++) acc[o][jj] = 0.0f;

    for (int ic = 0; ic < 32; ic++) {
#pragma unroll
        for (int di = 0; di < 3; di++) {
            const float* xr = &x0s[(ic*3 + di)*256 + j0];
            float4 xa = *(const float4*)xr;
            float2 xb = *(const float2*)(xr + 4);
            float x[6] = {xa.x, xa.y, xa.z, xa.w, xb.x, xb.y};
#pragma unroll
            for (int dj = 0; dj < 3; dj++) {
                float4 wv = *(const float4*)&w1s[((ic*3 + di)*3 + dj)*32 + og*4];
#pragma unroll
                for (int jj = 0; jj < 4; jj++) {
                    float xv = x[jj+dj];
                    acc[0][jj] += wv.x * xv;
                    acc[1][jj] += wv.y * xv;
                    acc[2][jj] += wv.z * xv;
                    acc[3][jj] += wv.w * xv;
                }
            }
        }
    }

#pragma unroll
    for (int o = 0; o < 4; o++) {
        int oc = half*32 + og*4 + o;
        float bias = __ldg(&b1[oc]);
        float4 v;
        v.x = fmaxf(acc[o][0] + bias, 0.0f);
        v.y = fmaxf(acc[o][1] + bias, 0.0f);
        v.z = fmaxf(acc[o][2] + bias, 0.0f);
        v.w = fmaxf(acc[o][3] + bias, 0.0f);
        *(float4*)&g_x1[(size_t)b*K_FC + ((size_t)oc*H1 + i)*W1 + j0] = v;
    }
}

/* ---------------- FC GEMM: C[40][32] = wr[40][K] * x1[32][K]^T ------------
 * grid = 252 K-chunks (KC=2304). Full 40x32 output tile per block; per-thread
 * 5 f-accumulators. smem tiles KT=64, float4 rows padded to 17. Partials go
 * to g_gpart and are reduced deterministically in gate_kernel. */
__global__ void fc_kernel(const float* __restrict__ wr) {
    __shared__ float4 wrs[FREQ*17];
    __shared__ float4 x1s[BB*17];
    int chunk = blockIdx.x;
    int tid   = threadIdx.x;
    int lane  = tid & 31;   /* b  */
    int wp    = tid >> 5;   /* f group: f = wp*5 + q */

    float acc[5] = {0.f, 0.f, 0.f, 0.f, 0.f};
    const float4* wr4 = (const float4*)wr;
    const float4* x14 = (const float4*)g_x1;
    int kb4 = (chunk*KC) >> 2;

    for (int kt = 0; kt < KC/KT; kt++) {
        int kt4 = kb4 + kt*(KT/4);
        for (int t = tid; t < FREQ*16; t += 256) {
            int r = t >> 4, c = t & 15;
            wrs[r*17 + c] = wr4[(size_t)r*(K_FC/4) + kt4 + c];
        }
        for (int t = tid; t < BB*16; t += 256) {
            int r = t >> 4, c = t & 15;
            x1s[r*17 + c] = x14[(size_t)r*(K_FC/4) + kt4 + c];
        }
        __syncthreads();
#pragma unroll
        for (int c = 0; c < 16; c++) {
            float4 xv = x1s[lane*17 + c];
#pragma unroll
            for (int q = 0; q < 5; q++) {
                float4 wv = wrs[(wp*5 + q)*17 + c];
                acc[q] += xv.x*wv.x;
                acc[q] += xv.y*wv.y;
                acc[q] += xv.z*wv.z;
                acc[q] += xv.w*wv.w;
            }
        }
        __syncthreads();
    }
#pragma unroll
    for (int q = 0; q < 5; q++) {
        int f = wp*5 + q;
        g_gpart[chunk*(FREQ*BB) + f*BB + lane] = acc[q];
    }
}

/* ---------------- reduce partials + bias + sigmoid ------------------------ */
__global__ void gate_kernel(const float* __restrict__ br) {
    int p = blockIdx.x*blockDim.x + threadIdx.x;  /* p = f*32 + b */
    if (p >= FREQ*BB) return;
    float s = 0.0f;
    for (int c = 0; c < NCHUNK; c++) s += g_gpart[c*(FREQ*BB) + p];
    int f = p >> 5;
    int b = p & 31;
    s += __ldg(&br[f]);
    g_gates[b*FREQ + f] = 1.0f / (1.0f + expf(-s));
}

/* ---------------- weighted mean of gates --------------------------------- */
__global__ void wtd_kernel(float* __restrict__ out, int out_size) {
    __shared__ float red[256];
    int tid = threadIdx.x;
    float s = 0.0f;
    for (int i = tid; i < BB*FREQ; i += 256) {
        int f = i % FREQ;
        s += g_gates[i] * (2.0f * (float)(f+1));
    }
    red[tid] = s;
    __syncthreads();
    for (int o = 128; o > 0; o >>= 1) {
        if (tid < o) red[tid] += red[tid + o];
        __syncthreads();
    }
    if (tid == 0) out[out_size - 1] = red[0] / (float)(BB*FREQ);
}

/* ---------------- projection: sin/cos dots, mag, gate scale -------------- */
__global__ void proj_kernel(float* __restrict__ out) {
    __shared__ float f0s[HH*(WW+1)];   /* 40 x 257, conflict-free */
    int b   = blockIdx.x;
    int tid = threadIdx.x;
    for (int t = tid; t < HH*WW; t += 256) {
        int h = t >> 8, w = t & 255;
        f0s[h*(WW+1) + w] = g_feats[((size_t)b*HH + h)*WW + w];
    }
    __syncthreads();
    for (int idx = tid; idx < FREQ*HH; idx += 256) {
        int f = idx / HH;
        int h = idx % HH;
        const float* sp = &g_sin[f*WW];
        const float* cp = &g_cos[f*WW];
        const float* xp = &f0s[h*(WW+1)];
        float s = 0.0f, c = 0.0f;
        for (int w = 0; w < WW; w++) {
            float v = xp[w];
            s += sp[w]*v;
            c += cp[w]*v;
        }
        s *= (1.0f/(float)WW);
        c *= (1.0f/(float)WW);
        float mag = sqrtf(s*s + c*c);
        out[(size_t)b*(FREQ*HH) + idx] = mag * g_gates[b*FREQ + f];
    }
}

/* ---------------- launch -------------------------------------------------- */
extern "C" void kernel_launch(void* const* d_in, const int* in_sizes, int n_in,
                              void* d_out, int out_size) {
    const float* in = (const float*)d_in[0];
    const float* w0 = (const float*)d_in[1];
    const float* b0 = (const float*)d_in[2];
    const float* w1 = (const float*)d_in[3];
    const float* b1 = (const float*)d_in[4];
    const float* wf = (const float*)d_in[5];
    const float* bf = (const float*)d_in[6];
    const float* wr = (const float*)d_in[7];
    const float* br = (const float*)d_in[8];
    float* out = (float*)d_out;

    cudaFuncSetAttribute(conv1_kernel,
                         cudaFuncAttributeMaxDynamicSharedMemorySize,
                         (288*32 + 32*3*256) * (int)sizeof(float));

    conv0_kernel<<<(BB*C0*H0*64)/256, 256>>>(in, w0, b0);
    feats_kernel<<<(BB*HH*WW + 255)/256, 256>>>(in, wf, bf);
    trig_kernel<<<FREQ, WW>>>();
    conv1_kernel<<<dim3(H1, BB, 2), 512, (288*32 + 32*3*256)*(int)sizeof(float)>>>(w1, b1);
    fc_kernel<<<NCHUNK, 256>>>(wr);
    gate_kernel<<<(FREQ*BB + 255)/256, 256>>>(br);
    wtd_kernel<<<1, 256>>>(out, out_size);
    proj_kernel<<<BB, 256>>>(out);
}

// round 2
// speedup vs baseline: 1.7773x; 1.7773x over previous
#include <cuda_runtime.h>
#include <math.h>
#include <stdint.h>

#define BB   32
#define HH   40
#define WW   256
#define FREQ 40
#define C0   32
#define H0   38
#define W0   254
#define C1   64
#define H1   36
#define W1   252
#define K_FC (C1*H1*W1)      /* 580608 */
#define KC   1152
#define NCHUNK 504           /* K_FC / KC */
#define KT   64
#define TWO_PI 6.28318530717958647692f

/* ---------------- scratch (device globals: no allocation allowed) -------- */
__device__ float g_x0[BB*C0*H0*W0];          /* conv0 output, ~39.5 MB */
__device__ float g_x1[(size_t)BB*K_FC];      /* conv1 output [b][k], ~74 MB */
__device__ float g_feats[BB*HH*WW];
__device__ float g_sin[FREQ*WW];
__device__ float g_cos[FREQ*WW];
__device__ float g_gpart[NCHUNK*FREQ*BB];
__device__ float g_gates[BB*FREQ];

/* ---------------- helpers ------------------------------------------------- */
__device__ __forceinline__ uint32_t f2tf32(float x) {
    uint32_t o;
    asm("cvt.rna.tf32.f32 %0, %1;" : "=r"(o) : "f"(x));
    return o;
}

__device__ __forceinline__ void mma_tf32(float c[4], const uint32_t a[4],
                                         const uint32_t b[2]) {
    asm volatile(
        "mma.sync.aligned.m16n8k8.row.col.f32.tf32.tf32.f32 "
        "{%0,%1,%2,%3}, {%4,%5,%6,%7}, {%8,%9}, {%0,%1,%2,%3};"
        : "+f"(c[0]), "+f"(c[1]), "+f"(c[2]), "+f"(c[3])
        : "r"(a[0]), "r"(a[1]), "r"(a[2]), "r"(a[3]), "r"(b[0]), "r"(b[1]));
}

/* ---------------- conv0: 1->32ch 3x3 VALID + bias + relu ----------------- */
__global__ void conv0_kernel(const float* __restrict__ in,
                             const float* __restrict__ w0,
                             const float* __restrict__ b0) {
    int idx = blockIdx.x*blockDim.x + threadIdx.x;
    int jg = idx & 63;
    int t  = idx >> 6;
    int i  = t % H0; t /= H0;
    int oc = t % C0; t /= C0;
    int b  = t;
    if (b >= BB) return;
    int j0 = jg*4;

    float w[9];
#pragma unroll
    for (int q = 0; q < 9; q++) w[q] = __ldg(&w0[oc*9+q]);

    float bias = __ldg(&b0[oc]);
    float acc0 = bias, acc1 = bias, acc2 = bias, acc3 = bias;

    const float* ip = in + (size_t)b*HH*WW;
#pragma unroll
    for (int di = 0; di < 3; di++) {
        const float* row = ip + (i+di)*WW;
        float x[6];
#pragma unroll
        for (int c = 0; c < 6; c++) x[c] = (j0+c < WW) ? row[j0+c] : 0.0f;
#pragma unroll
        for (int dj = 0; dj < 3; dj++) {
            float wv = w[di*3+dj];
            acc0 += wv * x[0+dj];
            acc1 += wv * x[1+dj];
            acc2 += wv * x[2+dj];
            acc3 += wv * x[3+dj];
        }
    }
    float* op = g_x0 + (((size_t)b*C0 + oc)*H0 + i)*W0 + j0;
    if (j0+0 < W0) op[0] = fmaxf(acc0, 0.0f);
    if (j0+1 < W0) op[1] = fmaxf(acc1, 0.0f);
    if (j0+2 < W0) op[2] = fmaxf(acc2, 0.0f);
    if (j0+3 < W0) op[3] = fmaxf(acc3, 0.0f);
}

/* ---------------- feats: 5-tap conv along W, zero pad, + bias ------------ */
__global__ void feats_kernel(const float* __restrict__ in,
                             const float* __restrict__ wf,
                             const float* __restrict__ bf) {
    int idx = blockIdx.x*blockDim.x + threadIdx.x;
    if (idx >= BB*HH*WW) return;
    int w = idx & (WW-1);
    const float* row = in + (idx - w);
    float acc = __ldg(&bf[0]);
#pragma unroll
    for (int t = 0; t < 5; t++) {
        int ww = w + t - 2;
        if (ww >= 0 && ww < WW) acc += __ldg(&wf[t]) * row[ww];
    }
    g_feats[idx] = acc;
}

/* ---------------- sin/cos phase tables ----------------------------------- */
__global__ void trig_kernel() {
    int f = blockIdx.x;
    int w = threadIdx.x;
    float fs = 2.0f * (float)(f+1);
    float t  = (0.5f/255.0f) * (float)w;
    float ph = TWO_PI * fs * t;
    g_sin[f*WW + w] = sinf(ph);
    g_cos[f*WW + w] = cosf(ph);
}

/* ---------------- conv1 via tf32 tensor cores ----------------------------
 * Per block (i, b): C[j=256pad][oc=64] = sum_{K=288} A * B
 * A slab in smem: xs[ic][di][j]  stride: ic*780 + di*260 + j  (tf32 bits)
 * B (weights transposed): ws[t9][oc][ic] stride: (t9*64+oc)*36 + ic
 * 8 warps: warp&3 -> 64-j block, warp>>2 -> 32-oc half.
 * Per k8-step per warp: 4 A-frags + 4 B-frags -> 16 mma.m16n8k8.tf32.
 * Bank-conflict free: A addr mod32 = 12*tig+gid (distinct), B = 4*gid+tig. */
#define XS_RS  260
#define XS_ICS 780
#define WS_ICS 36
#define SM_X   (32*XS_ICS)                  /* 24960 floats */
#define SM_W   (9*64*WS_ICS)                /* 20736 floats */
#define SM_TOT ((SM_X + SM_W)*4)            /* 182784 bytes */

__global__ void conv1_mma_kernel(const float* __restrict__ w1,
                                 const float* __restrict__ b1) {
    extern __shared__ float sm[];
    float* xs = sm;
    float* ws = sm + SM_X;

    int i   = blockIdx.x;
    int b   = blockIdx.y;
    int tid = threadIdx.x;

    /* stage transposed weights (tf32) */
    for (int t = tid; t < 9*64*32; t += 256) {
        int ic = t & 31;
        int oc = (t >> 5) & 63;
        int t9 = t >> 11;
        ws[(t9*64 + oc)*WS_ICS + ic] =
            __uint_as_float(f2tf32(__ldg(&w1[oc*288 + ic*9 + t9])));
    }
    /* zero right padding of xs (cols 254..259) */
    for (int t = tid; t < 32*3*6; t += 256) {
        int c = t % 6;
        int r = t / 6;              /* r = ic*3 + di */
        xs[r*XS_RS + 254 + c] = 0.0f;
    }
    /* stage x0 slab (tf32) */
    for (int t = tid; t < 32*3*254; t += 256) {
        int col = t % 254;
        int r   = t / 254;
        int di  = r % 3;
        int ic  = r / 3;
        xs[(ic*3 + di)*XS_RS + col] =
            __uint_as_float(f2tf32(g_x0[(((size_t)b*C0 + ic)*H0 + (i+di))*W0 + col]));
    }
    __syncthreads();

    int warp = tid >> 5;
    int lane = tid & 31;
    int mblk = warp & 3;      /* j block of 64  */
    int nhalf = warp >> 2;    /* oc half of 32  */
    int gid = lane >> 2;
    int tig = lane & 3;

    float cacc[4][4][4];
#pragma unroll
    for (int mf = 0; mf < 4; mf++)
#pragma unroll
        for (int nf = 0; nf < 4; nf++)
#pragma unroll
            for (int q = 0; q < 4; q++) cacc[mf][nf][q] = 0.0f;

#pragma unroll
    for (int t9 = 0; t9 < 9; t9++) {
        int di = t9 / 3, dj = t9 % 3;
        const float* xbase = xs + di*XS_RS + dj;
        const float* wbase = ws + (t9*64 + nhalf*32)*WS_ICS;
#pragma unroll
        for (int kc = 0; kc < 4; kc++) {
            int icb = kc*8;
            uint32_t bfrag[4][2];
#pragma unroll
            for (int nf = 0; nf < 4; nf++) {
                const float* p = wbase + (nf*8 + gid)*WS_ICS + icb + tig;
                bfrag[nf][0] = __float_as_uint(p[0]);
                bfrag[nf][1] = __float_as_uint(p[4]);
            }
            uint32_t afrag[4][4];
#pragma unroll
            for (int mf = 0; mf < 4; mf++) {
                int j0 = mblk*64 + mf*16 + gid;
                const float* p = xbase + (icb + tig)*XS_ICS + j0;
                afrag[mf][0] = __float_as_uint(p[0]);
                afrag[mf][1] = __float_as_uint(p[8]);
                afrag[mf][2] = __float_as_uint(p[4*XS_ICS]);
                afrag[mf][3] = __float_as_uint(p[4*XS_ICS + 8]);
            }
#pragma unroll
            for (int mf = 0; mf < 4; mf++)
#pragma unroll
                for (int nf = 0; nf < 4; nf++)
                    mma_tf32(cacc[mf][nf], afrag[mf], bfrag[nf]);
        }
    }

    /* epilogue: bias + relu + store to g_x1[b][oc][i][j] */
#pragma unroll
    for (int nf = 0; nf < 4; nf++) {
        int oc = nhalf*32 + nf*8 + tig*2;
        float bias0 = __ldg(&b1[oc]);
        float bias1 = __ldg(&b1[oc+1]);
        float* o0 = g_x1 + (size_t)b*K_FC + (size_t)oc*(H1*W1) + (size_t)i*W1;
        float* o1 = o0 + H1*W1;
#pragma unroll
        for (int mf = 0; mf < 4; mf++) {
            int j = mblk*64 + mf*16 + gid;
            if (j < W1) {
                o0[j] = fmaxf(cacc[mf][nf][0] + bias0, 0.0f);
                o1[j] = fmaxf(cacc[mf][nf][1] + bias1, 0.0f);
            }
            if (j + 8 < W1) {
                o0[j+8] = fmaxf(cacc[mf][nf][2] + bias0, 0.0f);
                o1[j+8] = fmaxf(cacc[mf][nf][3] + bias1, 0.0f);
            }
        }
    }
}

/* ---------------- FC GEMM: C[40][32] = wr[40][K] * x1[32][K]^T ------------ */
__global__ void fc_kernel(const float* __restrict__ wr) {
    __shared__ float4 wrs[FREQ*17];
    __shared__ float4 x1s[BB*17];
    int chunk = blockIdx.x;
    int tid   = threadIdx.x;
    int lane  = tid & 31;   /* b  */
    int wp    = tid >> 5;   /* f group: f = wp*5 + q */

    float acc[5] = {0.f, 0.f, 0.f, 0.f, 0.f};
    const float4* wr4 = (const float4*)wr;
    const float4* x14 = (const float4*)g_x1;
    int kb4 = (chunk*KC) >> 2;

    for (int kt = 0; kt < KC/KT; kt++) {
        int kt4 = kb4 + kt*(KT/4);
        for (int t = tid; t < FREQ*16; t += 256) {
            int r = t >> 4, c = t & 15;
            wrs[r*17 + c] = wr4[(size_t)r*(K_FC/4) + kt4 + c];
        }
        for (int t = tid; t < BB*16; t += 256) {
            int r = t >> 4, c = t & 15;
            x1s[r*17 + c] = x14[(size_t)r*(K_FC/4) + kt4 + c];
        }
        __syncthreads();
#pragma unroll
        for (int c = 0; c < 16; c++) {
            float4 xv = x1s[lane*17 + c];
#pragma unroll
            for (int q = 0; q < 5; q++) {
                float4 wv = wrs[(wp*5 + q)*17 + c];
                acc[q] += xv.x*wv.x;
                acc[q] += xv.y*wv.y;
                acc[q] += xv.z*wv.z;
                acc[q] += xv.w*wv.w;
            }
        }
        __syncthreads();
    }
#pragma unroll
    for (int q = 0; q < 5; q++) {
        int f = wp*5 + q;
        g_gpart[chunk*(FREQ*BB) + f*BB + lane] = acc[q];
    }
}

/* ---------------- reduce partials + bias + sigmoid ------------------------ */
__global__ void gate_kernel(const float* __restrict__ br) {
    int p = blockIdx.x*blockDim.x + threadIdx.x;  /* p = f*32 + b */
    if (p >= FREQ*BB) return;
    float s = 0.0f;
    for (int c = 0; c < NCHUNK; c++) s += g_gpart[c*(FREQ*BB) + p];
    int f = p >> 5;
    int b = p & 31;
    s += __ldg(&br[f]);
    g_gates[b*FREQ + f] = 1.0f / (1.0f + expf(-s));
}

/* ---------------- weighted mean of gates --------------------------------- */
__global__ void wtd_kernel(float* __restrict__ out, int out_size) {
    __shared__ float red[256];
    int tid = threadIdx.x;
    float s = 0.0f;
    for (int i = tid; i < BB*FREQ; i += 256) {
        int f = i % FREQ;
        s += g_gates[i] * (2.0f * (float)(f+1));
    }
    red[tid] = s;
    __syncthreads();
    for (int o = 128; o > 0; o >>= 1) {
        if (tid < o) red[tid] += red[tid + o];
        __syncthreads();
    }
    if (tid == 0) out[out_size - 1] = red[0] / (float)(BB*FREQ);
}

/* ---------------- projection: warp-per-dot, grid (b, f) ------------------ */
__global__ void proj_kernel(float* __restrict__ out) {
    int b = blockIdx.x;
    int f = blockIdx.y;
    int warp = threadIdx.x >> 5;
    int lane = threadIdx.x & 31;
    const float* sp = g_sin + f*WW;
    const float* cp = g_cos + f*WW;
    float gate = g_gates[b*FREQ + f];
    for (int h = warp; h < HH; h += 4) {
        const float* xp = g_feats + ((size_t)b*HH + h)*WW;
        float s = 0.0f, c = 0.0f;
#pragma unroll
        for (int q = 0; q < 8; q++) {
            int w = lane + q*32;
            float v = xp[w];
            s += sp[w]*v;
            c += cp[w]*v;
        }
#pragma unroll
        for (int o = 16; o > 0; o >>= 1) {
            s += __shfl_xor_sync(0xffffffffu, s, o);
            c += __shfl_xor_sync(0xffffffffu, c, o);
        }
        if (lane == 0) {
            s *= (1.0f/(float)WW);
            c *= (1.0f/(float)WW);
            out[(size_t)b*(FREQ*HH) + f*HH + h] = sqrtf(s*s + c*c) * gate;
        }
    }
}

/* ---------------- launch -------------------------------------------------- */
extern "C" void kernel_launch(void* const* d_in, const int* in_sizes, int n_in,
                              void* d_out, int out_size) {
    const float* in = (const float*)d_in[0];
    const float* w0 = (const float*)d_in[1];
    const float* b0 = (const float*)d_in[2];
    const float* w1 = (const float*)d_in[3];
    const float* b1 = (const float*)d_in[4];
    const float* wf = (const float*)d_in[5];
    const float* bf = (const float*)d_in[6];
    const float* wr = (const float*)d_in[7];
    const float* br = (const float*)d_in[8];
    float* out = (float*)d_out;

    cudaFuncSetAttribute(conv1_mma_kernel,
                         cudaFuncAttributeMaxDynamicSharedMemorySize, SM_TOT);

    conv0_kernel<<<(BB*C0*H0*64)/256, 256>>>(in, w0, b0);
    feats_kernel<<<(BB*HH*WW + 255)/256, 256>>>(in, wf, bf);
    trig_kernel<<<FREQ, WW>>>();
    conv1_mma_kernel<<<dim3(H1, BB), 256, SM_TOT>>>(w1, b1);
    fc_kernel<<<NCHUNK, 256>>>(wr);
    gate_kernel<<<(FREQ*BB + 255)/256, 256>>>(br);
    wtd_kernel<<<1, 256>>>(out, out_size);
    proj_kernel<<<dim3(BB, FREQ), 128>>>(out);
}

// round 4
// speedup vs baseline: 2.7199x; 1.5304x over previous
#include <cuda_runtime.h>
#include <cuda_bf16.h>
#include <math.h>
#include <stdint.h>

#define BB   32
#define HH   40
#define WW   256
#define FREQ 40
#define C0   32
#define H0   38
#define W0P  256                 /* padded x0 row stride */
#define C1   64
#define H1   36
#define W1   252
#define K_FC (C1*H1*W1)          /* 580608 */
#define KC   1152
#define NCHUNK 504               /* K_FC / KC */
#define KT   64
#define TWO_PI 6.28318530717958647692f

/* ---------------- scratch (device globals) ------------------------------- */
__device__ float        g_x0[(size_t)BB*C0*H0*W0P];   /* tf32-bits, padded */
__device__ __nv_bfloat16 g_x1h[(size_t)BB*K_FC];      /* conv1 out, bf16   */
__device__ uint2        g_wfrag[9*4*2*4*32];          /* w1 in frag order  */
__device__ float        g_feats[BB*HH*WW];
__device__ float        g_sin[FREQ*WW];
__device__ float        g_cos[FREQ*WW];
__device__ float        g_gpart[NCHUNK*FREQ*BB];
__device__ float        g_gates[BB*FREQ];

/* ---------------- helpers ------------------------------------------------- */
__device__ __forceinline__ uint32_t f2tf32(float x) {
    uint32_t o;
    asm("cvt.rna.tf32.f32 %0, %1;" : "=r"(o) : "f"(x));
    return o;
}

__device__ __forceinline__ void mma_tf32(float c[4], const uint32_t a[4],
                                         const uint32_t b[2]) {
    asm volatile(
        "mma.sync.aligned.m16n8k8.row.col.f32.tf32.tf32.f32 "
        "{%0,%1,%2,%3}, {%4,%5,%6,%7}, {%8,%9}, {%0,%1,%2,%3};"
        : "+f"(c[0]), "+f"(c[1]), "+f"(c[2]), "+f"(c[3])
        : "r"(a[0]), "r"(a[1]), "r"(a[2]), "r"(a[3]), "r"(b[0]), "r"(b[1]));
}

/* ---------------- weight prep: w1 -> tf32 fragment layout ---------------- */
__global__ void wprep_kernel(const float* __restrict__ w1) {
    int t = blockIdx.x*256 + threadIdx.x;       /* 9216 uint2 entries */
    if (t >= 9*4*2*4*32) return;
    int lane  = t & 31;
    int nf    = (t >> 5) & 3;
    int nhalf = (t >> 7) & 1;
    int kc    = (t >> 8) & 3;
    int t9    = t >> 10;
    int gid = lane >> 2, tig = lane & 3;
    int oc  = nhalf*32 + nf*8 + gid;
    int ic0 = kc*8 + tig;
    uint2 v;
    v.x = f2tf32(__ldg(&w1[oc*288 + ic0*9 + t9]));
    v.y = f2tf32(__ldg(&w1[oc*288 + (ic0+4)*9 + t9]));
    g_wfrag[t] = v;
}

/* ---------------- conv0: 1->32ch 3x3 VALID + bias + relu (tf32 out) ------ */
__global__ void conv0_kernel(const float* __restrict__ in,
                             const float* __restrict__ w0,
                             const float* __restrict__ b0) {
    int idx = blockIdx.x*blockDim.x + threadIdx.x;
    int jg = idx & 63;
    int t  = idx >> 6;
    int i  = t % H0; t /= H0;
    int oc = t % C0; t /= C0;
    int b  = t;
    if (b >= BB) return;
    int j0 = jg*4;

    float w[9];
#pragma unroll
    for (int q = 0; q < 9; q++) w[q] = __ldg(&w0[oc*9+q]);

    float bias = __ldg(&b0[oc]);
    float acc0 = bias, acc1 = bias, acc2 = bias, acc3 = bias;

    const float* ip = in + (size_t)b*HH*WW;
#pragma unroll
    for (int di = 0; di < 3; di++) {
        const float* row = ip + (i+di)*WW;
        float x[6];
#pragma unroll
        for (int c = 0; c < 6; c++) x[c] = (j0+c < WW) ? row[j0+c] : 0.0f;
#pragma unroll
        for (int dj = 0; dj < 3; dj++) {
            float wv = w[di*3+dj];
            acc0 += wv * x[0+dj];
            acc1 += wv * x[1+dj];
            acc2 += wv * x[2+dj];
            acc3 += wv * x[3+dj];
        }
    }
    float4 v;
    v.x = (j0+0 < 254) ? __uint_as_float(f2tf32(fmaxf(acc0, 0.0f))) : 0.0f;
    v.y = (j0+1 < 254) ? __uint_as_float(f2tf32(fmaxf(acc1, 0.0f))) : 0.0f;
    v.z = (j0+2 < 254) ? __uint_as_float(f2tf32(fmaxf(acc2, 0.0f))) : 0.0f;
    v.w = (j0+3 < 254) ? __uint_as_float(f2tf32(fmaxf(acc3, 0.0f))) : 0.0f;
    *(float4*)(g_x0 + (((size_t)b*C0 + oc)*H0 + i)*W0P + j0) = v;
}

/* ---------------- feats: 5-tap conv along W, zero pad, + bias ------------ */
__global__ void feats_kernel(const float* __restrict__ in,
                             const float* __restrict__ wf,
                             const float* __restrict__ bf) {
    int idx = blockIdx.x*blockDim.x + threadIdx.x;
    if (idx >= BB*HH*WW) return;
    int w = idx & (WW-1);
    const float* row = in + (idx - w);
    float acc = __ldg(&bf[0]);
#pragma unroll
    for (int t = 0; t < 5; t++) {
        int ww = w + t - 2;
        if (ww >= 0 && ww < WW) acc += __ldg(&wf[t]) * row[ww];
    }
    g_feats[idx] = acc;
}

/* ---------------- sin/cos phase tables ----------------------------------- */
__global__ void trig_kernel() {
    int f = blockIdx.x;
    int w = threadIdx.x;
    float fs = 2.0f * (float)(f+1);
    float t  = (0.5f/255.0f) * (float)w;
    float ph = TWO_PI * fs * t;
    g_sin[f*WW + w] = sinf(ph);
    g_cos[f*WW + w] = cosf(ph);
}

/* ---------------- conv1 via tf32 tensor cores ----------------------------
 * Per block (i, b): C[j=256pad][oc=64] over K=288 (9 taps x 32 ic).
 * xs smem slab: [ic][di][j] stride ic*780 + di*260 + j  (tf32 bits). 99.8KB
 * -> 2 CTAs/SM. B-fragments come straight from g_wfrag (coalesced, L1-hot).
 * 8 warps: warp&3 -> 64-j block, warp>>2 -> 32-oc half. Epilogue -> bf16. */
#define XS_RS  260
#define XS_ICS 780
#define SM_TOT (32*XS_ICS*4)     /* 99840 bytes */

__global__ void __launch_bounds__(256, 2)
conv1_mma_kernel(const float* __restrict__ b1) {
    extern __shared__ float xs[];

    int i   = blockIdx.x;
    int b   = blockIdx.y;
    int tid = threadIdx.x;

    /* stage x0 slab: pure float4 copy (already tf32 bits, 256-padded) */
    for (int t = tid; t < 32*3*64; t += 256) {
        int c4 = t & 63;
        int r  = t >> 6;            /* r = ic*3 + di */
        int di = r % 3;
        int ic = r / 3;
        float4 v = *(const float4*)(g_x0 +
            (((size_t)b*C0 + ic)*H0 + (i+di))*W0P + c4*4);
        *(float4*)(xs + r*XS_RS + c4*4) = v;
    }
    if (tid < 96) {   /* zero cols 256..259 of each of the 96 rows */
        float4 z = make_float4(0.f, 0.f, 0.f, 0.f);
        *(float4*)(xs + tid*XS_RS + 256) = z;
    }
    __syncthreads();

    int warp = tid >> 5;
    int lane = tid & 31;
    int mblk  = warp & 3;
    int nhalf = warp >> 2;
    int gid = lane >> 2;
    int tig = lane & 3;

    float cacc[4][4][4];
#pragma unroll
    for (int mf = 0; mf < 4; mf++)
#pragma unroll
        for (int nf = 0; nf < 4; nf++)
#pragma unroll
            for (int q = 0; q < 4; q++) cacc[mf][nf][q] = 0.0f;

#pragma unroll
    for (int t9 = 0; t9 < 9; t9++) {
        int di = t9 / 3, dj = t9 % 3;
        const float* xbase = xs + di*XS_RS + dj;
#pragma unroll
        for (int kc = 0; kc < 4; kc++) {
            int icb = kc*8;
            uint32_t bfrag[4][2];
            const uint2* wp = g_wfrag + (((t9*4 + kc)*2 + nhalf)*4)*32 + lane;
#pragma unroll
            for (int nf = 0; nf < 4; nf++) {
                uint2 v = __ldg(wp + nf*32);
                bfrag[nf][0] = v.x;
                bfrag[nf][1] = v.y;
            }
            uint32_t afrag[4][4];
#pragma unroll
            for (int mf = 0; mf < 4; mf++) {
                int j0 = mblk*64 + mf*16 + gid;
                const float* p = xbase + (icb + tig)*XS_ICS + j0;
                afrag[mf][0] = __float_as_uint(p[0]);
                afrag[mf][1] = __float_as_uint(p[8]);
                afrag[mf][2] = __float_as_uint(p[4*XS_ICS]);
                afrag[mf][3] = __float_as_uint(p[4*XS_ICS + 8]);
            }
#pragma unroll
            for (int mf = 0; mf < 4; mf++)
#pragma unroll
                for (int nf = 0; nf < 4; nf++)
                    mma_tf32(cacc[mf][nf], afrag[mf], bfrag[nf]);
        }
    }

    /* epilogue: bias + relu + bf16 store to g_x1h[b][oc][i][j] */
#pragma unroll
    for (int nf = 0; nf < 4; nf++) {
        int oc = nhalf*32 + nf*8 + tig*2;
        float bias0 = __ldg(&b1[oc]);
        float bias1 = __ldg(&b1[oc+1]);
        __nv_bfloat16* o0 = g_x1h + (size_t)b*K_FC + (size_t)oc*(H1*W1) + (size_t)i*W1;
        __nv_bfloat16* o1 = o0 + H1*W1;
#pragma unroll
        for (int mf = 0; mf < 4; mf++) {
            int j = mblk*64 + mf*16 + gid;
            if (j < W1) {
                o0[j] = __float2bfloat16_rn(fmaxf(cacc[mf][nf][0] + bias0, 0.0f));
                o1[j] = __float2bfloat16_rn(fmaxf(cacc[mf][nf][1] + bias1, 0.0f));
            }
            if (j + 8 < W1) {
                o0[j+8] = __float2bfloat16_rn(fmaxf(cacc[mf][nf][2] + bias0, 0.0f));
                o1[j+8] = __float2bfloat16_rn(fmaxf(cacc[mf][nf][3] + bias1, 0.0f));
            }
        }
    }
}

/* ---------------- FC GEMM: C[40][32] = wr[40][K] * x1[32][K]^T ------------ */
__global__ void fc_kernel(const float* __restrict__ wr) {
    __shared__ float4 wrs[FREQ*17];
    __shared__ float4 x1s[BB*17];
    int chunk = blockIdx.x;
    int tid   = threadIdx.x;
    int lane  = tid & 31;   /* b */
    int wp    = tid >> 5;   /* f = wp*5 + q */

    float acc[5] = {0.f, 0.f, 0.f, 0.f, 0.f};
    const float4* wr4 = (const float4*)wr;
    int kb = chunk*KC;

    for (int kt = 0; kt < KC/KT; kt++) {
        int k0 = kb + kt*KT;
        for (int t = tid; t < FREQ*16; t += 256) {
            int r = t >> 4, c = t & 15;
            wrs[r*17 + c] = wr4[(size_t)r*(K_FC/4) + (k0 >> 2) + c];
        }
        for (int t = tid; t < BB*16; t += 256) {
            int r = t >> 4, c = t & 15;
            const __nv_bfloat162* p =
                (const __nv_bfloat162*)(g_x1h + (size_t)r*K_FC + k0 + c*4);
            float2 lo = __bfloat1622float2(p[0]);
            float2 hi = __bfloat1622float2(p[1]);
            x1s[r*17 + c] = make_float4(lo.x, lo.y, hi.x, hi.y);
        }
        __syncthreads();
#pragma unroll
        for (int c = 0; c < 16; c++) {
            float4 xv = x1s[lane*17 + c];
#pragma unroll
            for (int q = 0; q < 5; q++) {
                float4 wv = wrs[(wp*5 + q)*17 + c];
                acc[q] += xv.x*wv.x;
                acc[q] += xv.y*wv.y;
                acc[q] += xv.z*wv.z;
                acc[q] += xv.w*wv.w;
            }
        }
        __syncthreads();
    }
#pragma unroll
    for (int q = 0; q < 5; q++) {
        int f = wp*5 + q;
        g_gpart[chunk*(FREQ*BB) + f*BB + lane] = acc[q];
    }
}

/* ---------------- reduce partials + bias + sigmoid ------------------------ */
__global__ void gate_kernel(const float* __restrict__ br) {
    int p = blockIdx.x*blockDim.x + threadIdx.x;  /* p = f*32 + b */
    if (p >= FREQ*BB) return;
    float s = 0.0f;
    for (int c = 0; c < NCHUNK; c++) s += g_gpart[c*(FREQ*BB) + p];
    int f = p >> 5;
    int b = p & 31;
    s += __ldg(&br[f]);
    g_gates[b*FREQ + f] = 1.0f / (1.0f + expf(-s));
}

/* ---------------- weighted mean of gates --------------------------------- */
__global__ void wtd_kernel(float* __restrict__ out, int out_size) {
    __shared__ float red[256];
    int tid = threadIdx.x;
    float s = 0.0f;
    for (int i = tid; i < BB*FREQ; i += 256) {
        int f = i % FREQ;
        s += g_gates[i] * (2.0f * (float)(f+1));
    }
    red[tid] = s;
    __syncthreads();
    for (int o = 128; o > 0; o >>= 1) {
        if (tid < o) red[tid] += red[tid + o];
        __syncthreads();
    }
    if (tid == 0) out[out_size - 1] = red[0] / (float)(BB*FREQ);
}

/* ---------------- projection: warp-per-dot, grid (b, f) ------------------ */
__global__ void proj_kernel(float* __restrict__ out) {
    int b = blockIdx.x;
    int f = blockIdx.y;
    int warp = threadIdx.x >> 5;
    int lane = threadIdx.x & 31;
    const float* sp = g_sin + f*WW;
    const float* cp = g_cos + f*WW;
    float gate = g_gates[b*FREQ + f];
    for (int h = warp; h < HH; h += 4) {
        const float* xp = g_feats + ((size_t)b*HH + h)*WW;
        float s = 0.0f, c = 0.0f;
#pragma unroll
        for (int q = 0; q < 8; q++) {
            int w = lane + q*32;
            float v = xp[w];
            s += sp[w]*v;
            c += cp[w]*v;
        }
#pragma unroll
        for (int o = 16; o > 0; o >>= 1) {
            s += __shfl_xor_sync(0xffffffffu, s, o);
            c += __shfl_xor_sync(0xffffffffu, c, o);
        }
        if (lane == 0) {
            s *= (1.0f/(float)WW);
            c *= (1.0f/(float)WW);
            out[(size_t)b*(FREQ*HH) + f*HH + h] = sqrtf(s*s + c*c) * gate;
        }
    }
}

/* ---------------- launch -------------------------------------------------- */
extern "C" void kernel_launch(void* const* d_in, const int* in_sizes, int n_in,
                              void* d_out, int out_size) {
    const float* in = (const float*)d_in[0];
    const float* w0 = (const float*)d_in[1];
    const float* b0 = (const float*)d_in[2];
    const float* w1 = (const float*)d_in[3];
    const float* b1 = (const float*)d_in[4];
    const float* wf = (const float*)d_in[5];
    const float* bf = (const float*)d_in[6];
    const float* wr = (const float*)d_in[7];
    const float* br = (const float*)d_in[8];
    float* out = (float*)d_out;

    cudaFuncSetAttribute(conv1_mma_kernel,
                         cudaFuncAttributeMaxDynamicSharedMemorySize, SM_TOT);

    wprep_kernel<<<36, 256>>>(w1);
    conv0_kernel<<<(BB*C0*H0*64)/256, 256>>>(in, w0, b0);
    feats_kernel<<<(BB*HH*WW + 255)/256, 256>>>(in, wf, bf);
    trig_kernel<<<FREQ, WW>>>();
    conv1_mma_kernel<<<dim3(H1, BB), 256, SM_TOT>>>(b1);
    fc_kernel<<<NCHUNK, 256>>>(wr);
    gate_kernel<<<(FREQ*BB + 255)/256, 256>>>(br);
    wtd_kernel<<<1, 256>>>(out, out_size);
    proj_kernel<<<dim3(BB, FREQ), 128>>>(out);
}

// round 5
// speedup vs baseline: 2.9977x; 1.1021x over previous
#include <cuda_runtime.h>
#include <cuda_bf16.h>
#include <math.h>
#include <stdint.h>

#define BB   32
#define HH   40
#define WW   256
#define FREQ 40
#define C0   32
#define H0   38
#define C1   64
#define H1   36
#define W1   252
#define K_FC (C1*H1*W1)          /* 580608 */
#define KC   1152
#define NCHUNK 504               /* K_FC / KC */
#define KT   64
#define TWO_PI 6.28318530717958647692f

/* ---------------- scratch (device globals) ------------------------------- */
/* x0 packed: [b][icp(16)][i(38)][j(256)] u32 = bf16x2 (ic even lo, odd hi) */
__device__ uint32_t      g_x0p[(size_t)BB*16*H0*256];
__device__ __nv_bfloat16 g_x1h[(size_t)BB*K_FC];      /* conv1 out, bf16   */
__device__ uint2         g_wfragh[9*2*4*2*32];        /* w1 bf16 frag order */
__device__ float         g_feats[BB*HH*WW];
__device__ float         g_gpart[NCHUNK*FREQ*BB];
__device__ float         g_gates[BB*FREQ];

/* ---------------- helpers ------------------------------------------------- */
__device__ __forceinline__ uint32_t packbf2(float lo, float hi) {
    __nv_bfloat162 h = __floats2bfloat162_rn(lo, hi);
    return *(uint32_t*)&h;
}

__device__ __forceinline__ void mma_bf16(float c[4], const uint32_t a[4],
                                         const uint32_t b[2]) {
    asm volatile(
        "mma.sync.aligned.m16n8k16.row.col.f32.bf16.bf16.f32 "
        "{%0,%1,%2,%3}, {%4,%5,%6,%7}, {%8,%9}, {%0,%1,%2,%3};"
        : "+f"(c[0]), "+f"(c[1]), "+f"(c[2]), "+f"(c[3])
        : "r"(a[0]), "r"(a[1]), "r"(a[2]), "r"(a[3]), "r"(b[0]), "r"(b[1]));
}

/* ---------------- weight prep: w1 -> bf16 fragment layout ----------------
 * index: [t9(9)][kh(2)][nq(4)][nf(2)][lane(32)] -> uint2
 * v.x = (ic0 lo, ic0+1 hi), v.y = (ic0+8 lo, ic0+9 hi), ic0 = 2*tig+16*kh */
__global__ void wprep_kernel(const float* __restrict__ w1) {
    int t = blockIdx.x*256 + threadIdx.x;     /* 4608 entries */
    if (t >= 9*2*4*2*32) return;
    int lane = t & 31;
    int nf   = (t >> 5) & 1;
    int nq   = (t >> 6) & 3;
    int kh   = (t >> 8) & 1;
    int t9   = t >> 9;
    int gid = lane >> 2, tig = lane & 3;
    int oc  = nq*16 + nf*8 + gid;
    int ic0 = 2*tig + 16*kh;
    uint2 v;
    v.x = packbf2(__ldg(&w1[oc*288 + (ic0  )*9 + t9]),
                  __ldg(&w1[oc*288 + (ic0+1)*9 + t9]));
    v.y = packbf2(__ldg(&w1[oc*288 + (ic0+8)*9 + t9]),
                  __ldg(&w1[oc*288 + (ic0+9)*9 + t9]));
    g_wfragh[t] = v;
}

/* ---------------- conv0: 1->32ch 3x3 VALID + bias + relu (bf16x2 out) ---- */
__global__ void conv0_kernel(const float* __restrict__ in,
                             const float* __restrict__ w0,
                             const float* __restrict__ b0) {
    int idx = blockIdx.x*blockDim.x + threadIdx.x;
    int jg = idx & 63;
    int t  = idx >> 6;
    int i  = t % H0;  t /= H0;
    int op = t % 16;  t /= 16;      /* oc pair */
    int b  = t;
    if (b >= BB) return;
    int j0 = jg*4;
    int oc0 = op*2;

    float wA[9], wB[9];
#pragma unroll
    for (int q = 0; q < 9; q++) {
        wA[q] = __ldg(&w0[oc0*9+q]);
        wB[q] = __ldg(&w0[(oc0+1)*9+q]);
    }
    float biasA = __ldg(&b0[oc0]);
    float biasB = __ldg(&b0[oc0+1]);
    float aA[4] = {biasA, biasA, biasA, biasA};
    float aB[4] = {biasB, biasB, biasB, biasB};

    const float* ip = in + (size_t)b*HH*WW;
#pragma unroll
    for (int di = 0; di < 3; di++) {
        const float* row = ip + (i+di)*WW;
        float x[6];
#pragma unroll
        for (int c = 0; c < 6; c++) x[c] = (j0+c < WW) ? row[j0+c] : 0.0f;
#pragma unroll
        for (int dj = 0; dj < 3; dj++) {
            float wa = wA[di*3+dj], wb = wB[di*3+dj];
#pragma unroll
            for (int q = 0; q < 4; q++) {
                aA[q] += wa * x[q+dj];
                aB[q] += wb * x[q+dj];
            }
        }
    }
    uint4 v;
    uint32_t* vp = &v.x;
#pragma unroll
    for (int q = 0; q < 4; q++) {
        bool ok = (j0+q < 254);
        vp[q] = packbf2(ok ? fmaxf(aA[q], 0.0f) : 0.0f,
                        ok ? fmaxf(aB[q], 0.0f) : 0.0f);
    }
    *(uint4*)(g_x0p + (((size_t)b*16 + op)*H0 + i)*256 + j0) = v;
}

/* ---------------- feats: 5-tap conv along W, zero pad, + bias ------------ */
__global__ void feats_kernel(const float* __restrict__ in,
                             const float* __restrict__ wf,
                             const float* __restrict__ bf) {
    int idx = blockIdx.x*blockDim.x + threadIdx.x;
    if (idx >= BB*HH*WW) return;
    int w = idx & (WW-1);
    const float* row = in + (idx - w);
    float acc = __ldg(&bf[0]);
#pragma unroll
    for (int t = 0; t < 5; t++) {
        int ww = w + t - 2;
        if (ww >= 0 && ww < WW) acc += __ldg(&wf[t]) * row[ww];
    }
    g_feats[idx] = acc;
}

/* ---------------- conv1 via bf16 m16n8k16 tensor cores -------------------
 * Per block (i, b): C[j=256pad][oc=64] over K=288 (9 taps x 32 ic).
 * xsp smem: [icp(16)][di(3)][j(260)] u32 bf16x2, 48.8KB -> 2 CTAs/SM.
 * 16 warps: warp&3 -> 64-j block (4 mf), warp>>2 -> 16-oc quarter (2 nf).
 * 18 k16-steps; per step per warp: 1 LDG.64x2 + 16 LDS.32 + 8 MMA. */
#define XS_RS  260
#define SM_TOT (16*3*XS_RS*4)    /* 49920 bytes */

__global__ void __launch_bounds__(512, 2)
conv1_mma_kernel(const float* __restrict__ b1) {
    extern __shared__ uint32_t xsp[];

    int i   = blockIdx.x;
    int b   = blockIdx.y;
    int tid = threadIdx.x;

    /* stage x0p slab: raw uint4 copy */
    for (int t = tid; t < 48*64; t += 512) {
        int c4 = t & 63;
        int r  = t >> 6;            /* r = icp*3 + di */
        int di = r % 3;
        int ic = r / 3;
        uint4 v = *(const uint4*)(g_x0p +
            (((size_t)b*16 + ic)*H0 + (i+di))*256 + c4*4);
        *(uint4*)(xsp + r*XS_RS + c4*4) = v;
    }
    if (tid < 48) {   /* zero cols 256..259 */
        uint4 z = make_uint4(0u, 0u, 0u, 0u);
        *(uint4*)(xsp + tid*XS_RS + 256) = z;
    }
    __syncthreads();

    int warp = tid >> 5;
    int lane = tid & 31;
    int mblk = warp & 3;
    int nq   = warp >> 2;
    int gid = lane >> 2;
    int tig = lane & 3;

    float cacc[4][2][4];
#pragma unroll
    for (int mf = 0; mf < 4; mf++)
#pragma unroll
        for (int nf = 0; nf < 2; nf++)
#pragma unroll
            for (int q = 0; q < 4; q++) cacc[mf][nf][q] = 0.0f;

#pragma unroll
    for (int t9 = 0; t9 < 9; t9++) {
        int di = t9 / 3, dj = t9 % 3;
#pragma unroll
        for (int kh = 0; kh < 2; kh++) {
            uint32_t bfrag[2][2];
            const uint2* wp = g_wfragh + ((((t9*2 + kh)*4 + nq)*2)*32) + lane;
            {
                uint2 v0 = __ldg(wp);
                uint2 v1 = __ldg(wp + 32);
                bfrag[0][0] = v0.x; bfrag[0][1] = v0.y;
                bfrag[1][0] = v1.x; bfrag[1][1] = v1.y;
            }
            const uint32_t* xa = xsp + ((kh*8 + tig    )*3 + di)*XS_RS + dj;
            const uint32_t* xb = xsp + ((kh*8 + tig + 4)*3 + di)*XS_RS + dj;
#pragma unroll
            for (int mf = 0; mf < 4; mf++) {
                int j0 = mblk*64 + mf*16 + gid;
                uint32_t afrag[4];
                afrag[0] = xa[j0];
                afrag[1] = xa[j0 + 8];
                afrag[2] = xb[j0];
                afrag[3] = xb[j0 + 8];
                mma_bf16(cacc[mf][0], afrag, bfrag[0]);
                mma_bf16(cacc[mf][1], afrag, bfrag[1]);
            }
        }
    }

    /* epilogue: bias + relu + bf16 store to g_x1h[b][oc][i][j] */
#pragma unroll
    for (int nf = 0; nf < 2; nf++) {
        int oc = nq*16 + nf*8 + tig*2;
        float bias0 = __ldg(&b1[oc]);
        float bias1 = __ldg(&b1[oc+1]);
        __nv_bfloat16* o0 = g_x1h + (size_t)b*K_FC + (size_t)oc*(H1*W1) + (size_t)i*W1;
        __nv_bfloat16* o1 = o0 + H1*W1;
#pragma unroll
        for (int mf = 0; mf < 4; mf++) {
            int j = mblk*64 + mf*16 + gid;
            if (j < W1) {
                o0[j] = __float2bfloat16_rn(fmaxf(cacc[mf][nf][0] + bias0, 0.0f));
                o1[j] = __float2bfloat16_rn(fmaxf(cacc[mf][nf][1] + bias1, 0.0f));
            }
            if (j + 8 < W1) {
                o0[j+8] = __float2bfloat16_rn(fmaxf(cacc[mf][nf][2] + bias0, 0.0f));
                o1[j+8] = __float2bfloat16_rn(fmaxf(cacc[mf][nf][3] + bias1, 0.0f));
            }
        }
    }
}

/* ---------------- FC GEMM: C[40][32] = wr[40][K] * x1[32][K]^T ------------ */
__global__ void fc_kernel(const float* __restrict__ wr) {
    __shared__ float4 wrs[FREQ*17];
    __shared__ float4 x1s[BB*17];
    int chunk = blockIdx.x;
    int tid   = threadIdx.x;
    int lane  = tid & 31;   /* b */
    int wp    = tid >> 5;   /* f = wp*5 + q */

    float acc[5] = {0.f, 0.f, 0.f, 0.f, 0.f};
    const float4* wr4 = (const float4*)wr;
    int kb = chunk*KC;

    for (int kt = 0; kt < KC/KT; kt++) {
        int k0 = kb + kt*KT;
        for (int t = tid; t < FREQ*16; t += 256) {
            int r = t >> 4, c = t & 15;
            wrs[r*17 + c] = wr4[(size_t)r*(K_FC/4) + (k0 >> 2) + c];
        }
        for (int t = tid; t < BB*16; t += 256) {
            int r = t >> 4, c = t & 15;
            const __nv_bfloat162* p =
                (const __nv_bfloat162*)(g_x1h + (size_t)r*K_FC + k0 + c*4);
            float2 lo = __bfloat1622float2(p[0]);
            float2 hi = __bfloat1622float2(p[1]);
            x1s[r*17 + c] = make_float4(lo.x, lo.y, hi.x, hi.y);
        }
        __syncthreads();
#pragma unroll
        for (int c = 0; c < 16; c++) {
            float4 xv = x1s[lane*17 + c];
#pragma unroll
            for (int q = 0; q < 5; q++) {
                float4 wv = wrs[(wp*5 + q)*17 + c];
                acc[q] += xv.x*wv.x;
                acc[q] += xv.y*wv.y;
                acc[q] += xv.z*wv.z;
                acc[q] += xv.w*wv.w;
            }
        }
        __syncthreads();
    }
#pragma unroll
    for (int q = 0; q < 5; q++) {
        int f = wp*5 + q;
        g_gpart[chunk*(FREQ*BB) + f*BB + lane] = acc[q];
    }
}

/* ---------------- reduce partials + bias + sigmoid ------------------------ */
__global__ void gate_kernel(const float* __restrict__ br) {
    int p = blockIdx.x*blockDim.x + threadIdx.x;  /* p = f*32 + b */
    if (p >= FREQ*BB) return;
    float s = 0.0f;
    for (int c = 0; c < NCHUNK; c++) s += g_gpart[c*(FREQ*BB) + p];
    int f = p >> 5;
    int b = p & 31;
    s += __ldg(&br[f]);
    g_gates[b*FREQ + f] = 1.0f / (1.0f + expf(-s));
}

/* ---------------- weighted mean of gates --------------------------------- */
__global__ void wtd_kernel(float* __restrict__ out, int out_size) {
    __shared__ float red[256];
    int tid = threadIdx.x;
    float s = 0.0f;
    for (int i = tid; i < BB*FREQ; i += 256) {
        int f = i % FREQ;
        s += g_gates[i] * (2.0f * (float)(f+1));
    }
    red[tid] = s;
    __syncthreads();
    for (int o = 128; o > 0; o >>= 1) {
        if (tid < o) red[tid] += red[tid + o];
        __syncthreads();
    }
    if (tid == 0) out[out_size - 1] = red[0] / (float)(BB*FREQ);
}

/* ---------------- projection (trig fused): grid (b, f), 128 thr ---------- */
__global__ void proj_kernel(float* __restrict__ out) {
    __shared__ float sp[WW];
    __shared__ float cp[WW];
    int b = blockIdx.x;
    int f = blockIdx.y;
    int tid  = threadIdx.x;
    int warp = tid >> 5;
    int lane = tid & 31;

    float fs = 2.0f * (float)(f+1);
#pragma unroll
    for (int q = 0; q < 2; q++) {
        int w = tid + q*128;
        float t  = (0.5f/255.0f) * (float)w;
        float ph = TWO_PI * fs * t;
        float sv, cv;
        sincosf(ph, &sv, &cv);
        sp[w] = sv;
        cp[w] = cv;
    }
    __syncthreads();

    float gate = g_gates[b*FREQ + f];
    for (int h = warp; h < HH; h += 4) {
        const float* xp = g_feats + ((size_t)b*HH + h)*WW;
        float s = 0.0f, c = 0.0f;
#pragma unroll
        for (int q = 0; q < 8; q++) {
            int w = lane + q*32;
            float v = xp[w];
            s += sp[w]*v;
            c += cp[w]*v;
        }
#pragma unroll
        for (int o = 16; o > 0; o >>= 1) {
            s += __shfl_xor_sync(0xffffffffu, s, o);
            c += __shfl_xor_sync(0xffffffffu, c, o);
        }
        if (lane == 0) {
            s *= (1.0f/(float)WW);
            c *= (1.0f/(float)WW);
            out[(size_t)b*(FREQ*HH) + f*HH + h] = sqrtf(s*s + c*c) * gate;
        }
    }
}

/* ---------------- launch -------------------------------------------------- */
extern "C" void kernel_launch(void* const* d_in, const int* in_sizes, int n_in,
                              void* d_out, int out_size) {
    const float* in = (const float*)d_in[0];
    const float* w0 = (const float*)d_in[1];
    const float* b0 = (const float*)d_in[2];
    const float* w1 = (const float*)d_in[3];
    const float* b1 = (const float*)d_in[4];
    const float* wf = (const float*)d_in[5];
    const float* bf = (const float*)d_in[6];
    const float* wr = (const float*)d_in[7];
    const float* br = (const float*)d_in[8];
    float* out = (float*)d_out;

    cudaFuncSetAttribute(conv1_mma_kernel,
                         cudaFuncAttributeMaxDynamicSharedMemorySize, SM_TOT);

    wprep_kernel<<<18, 256>>>(w1);
    conv0_kernel<<<(BB*16*H0*64)/256, 256>>>(in, w0, b0);
    feats_kernel<<<(BB*HH*WW + 255)/256, 256>>>(in, wf, bf);
    conv1_mma_kernel<<<dim3(H1, BB), 512, SM_TOT>>>(b1);
    fc_kernel<<<NCHUNK, 256>>>(wr);
    gate_kernel<<<(FREQ*BB + 255)/256, 256>>>(br);
    wtd_kernel<<<1, 256>>>(out, out_size);
    proj_kernel<<<dim3(BB, FREQ), 128>>>(out);
}

// round 6
// speedup vs baseline: 3.1027x; 1.0350x over previous
#include <cuda_runtime.h>
#include <cuda_bf16.h>
#include <math.h>
#include <stdint.h>

#define BB   32
#define HH   40
#define WW   256
#define FREQ 40
#define C0   32
#define H0   38
#define C1   64
#define H1   36
#define W1   252
#define K_FC (C1*H1*W1)          /* 580608 */
#define KC   1152
#define NCHUNK 504               /* K_FC / KC */
#define TWO_PI 6.28318530717958647692f

/* ---------------- scratch (device globals) ------------------------------- */
/* x0 packed: [b][icp(16)][i(38)][j(256)] u32 = bf16x2 (ic even lo, odd hi) */
__device__ uint32_t      g_x0p[(size_t)BB*16*H0*256];
__device__ __nv_bfloat16 g_x1h[(size_t)BB*K_FC];      /* conv1 out, bf16   */
__device__ uint2         g_wfragh[9*2*4*2*32];        /* w1 bf16 frag order */
__device__ float         g_feats[BB*HH*WW];
__device__ float         g_gpart[NCHUNK*FREQ*BB];
__device__ float         g_gates[BB*FREQ];

/* ---------------- helpers ------------------------------------------------- */
__device__ __forceinline__ uint32_t packbf2(float lo, float hi) {
    __nv_bfloat162 h = __floats2bfloat162_rn(lo, hi);
    return *(uint32_t*)&h;
}

__device__ __forceinline__ void mma_bf16(float c[4], const uint32_t a[4],
                                         const uint32_t b[2]) {
    asm volatile(
        "mma.sync.aligned.m16n8k16.row.col.f32.bf16.bf16.f32 "
        "{%0,%1,%2,%3}, {%4,%5,%6,%7}, {%8,%9}, {%0,%1,%2,%3};"
        : "+f"(c[0]), "+f"(c[1]), "+f"(c[2]), "+f"(c[3])
        : "r"(a[0]), "r"(a[1]), "r"(a[2]), "r"(a[3]), "r"(b[0]), "r"(b[1]));
}

/* ---------------- weight prep: w1 -> bf16 fragment layout ----------------
 * index: [t9(9)][kh(2)][nq(4)][nf(2)][lane(32)] -> uint2 */
__global__ void wprep_kernel(const float* __restrict__ w1) {
    int t = blockIdx.x*256 + threadIdx.x;     /* 4608 entries */
    if (t >= 9*2*4*2*32) return;
    int lane = t & 31;
    int nf   = (t >> 5) & 1;
    int nq   = (t >> 6) & 3;
    int kh   = (t >> 8) & 1;
    int t9   = t >> 9;
    int gid = lane >> 2, tig = lane & 3;
    int oc  = nq*16 + nf*8 + gid;
    int ic0 = 2*tig + 16*kh;
    uint2 v;
    v.x = packbf2(__ldg(&w1[oc*288 + (ic0  )*9 + t9]),
                  __ldg(&w1[oc*288 + (ic0+1)*9 + t9]));
    v.y = packbf2(__ldg(&w1[oc*288 + (ic0+8)*9 + t9]),
                  __ldg(&w1[oc*288 + (ic0+9)*9 + t9]));
    g_wfragh[t] = v;
}

/* ---------------- conv0: 1->32ch 3x3 VALID + bias + relu (bf16x2 out) ---- */
__global__ void conv0_kernel(const float* __restrict__ in,
                             const float* __restrict__ w0,
                             const float* __restrict__ b0) {
    int idx = blockIdx.x*blockDim.x + threadIdx.x;
    int jg = idx & 63;
    int t  = idx >> 6;
    int i  = t % H0;  t /= H0;
    int op = t % 16;  t /= 16;      /* oc pair */
    int b  = t;
    if (b >= BB) return;
    int j0 = jg*4;
    int oc0 = op*2;

    float wA[9], wB[9];
#pragma unroll
    for (int q = 0; q < 9; q++) {
        wA[q] = __ldg(&w0[oc0*9+q]);
        wB[q] = __ldg(&w0[(oc0+1)*9+q]);
    }
    float biasA = __ldg(&b0[oc0]);
    float biasB = __ldg(&b0[oc0+1]);
    float aA[4] = {biasA, biasA, biasA, biasA};
    float aB[4] = {biasB, biasB, biasB, biasB};

    const float* ip = in + (size_t)b*HH*WW;
#pragma unroll
    for (int di = 0; di < 3; di++) {
        const float* row = ip + (i+di)*WW;
        float x[6];
#pragma unroll
        for (int c = 0; c < 6; c++) x[c] = (j0+c < WW) ? row[j0+c] : 0.0f;
#pragma unroll
        for (int dj = 0; dj < 3; dj++) {
            float wa = wA[di*3+dj], wb = wB[di*3+dj];
#pragma unroll
            for (int q = 0; q < 4; q++) {
                aA[q] += wa * x[q+dj];
                aB[q] += wb * x[q+dj];
            }
        }
    }
    uint4 v;
    uint32_t* vp = &v.x;
#pragma unroll
    for (int q = 0; q < 4; q++) {
        bool ok = (j0+q < 254);
        vp[q] = packbf2(ok ? fmaxf(aA[q], 0.0f) : 0.0f,
                        ok ? fmaxf(aB[q], 0.0f) : 0.0f);
    }
    *(uint4*)(g_x0p + (((size_t)b*16 + op)*H0 + i)*256 + j0) = v;
}

/* ---------------- feats: 5-tap conv along W, zero pad, + bias ------------ */
__global__ void feats_kernel(const float* __restrict__ in,
                             const float* __restrict__ wf,
                             const float* __restrict__ bf) {
    int idx = blockIdx.x*blockDim.x + threadIdx.x;
    if (idx >= BB*HH*WW) return;
    int w = idx & (WW-1);
    const float* row = in + (idx - w);
    float acc = __ldg(&bf[0]);
#pragma unroll
    for (int t = 0; t < 5; t++) {
        int ww = w + t - 2;
        if (ww >= 0 && ww < WW) acc += __ldg(&wf[t]) * row[ww];
    }
    g_feats[idx] = acc;
}

/* ---------------- conv1 via bf16 m16n8k16 tensor cores ------------------- */
#define XS_RS  260
#define SM_TOT (16*3*XS_RS*4)    /* 49920 bytes */

__global__ void __launch_bounds__(512, 2)
conv1_mma_kernel(const float* __restrict__ b1) {
    extern __shared__ uint32_t xsp[];

    int i   = blockIdx.x;
    int b   = blockIdx.y;
    int tid = threadIdx.x;

    /* stage x0p slab: raw uint4 copy */
    for (int t = tid; t < 48*64; t += 512) {
        int c4 = t & 63;
        int r  = t >> 6;            /* r = icp*3 + di */
        int di = r % 3;
        int ic = r / 3;
        uint4 v = *(const uint4*)(g_x0p +
            (((size_t)b*16 + ic)*H0 + (i+di))*256 + c4*4);
        *(uint4*)(xsp + r*XS_RS + c4*4) = v;
    }
    if (tid < 48) {   /* zero cols 256..259 */
        uint4 z = make_uint4(0u, 0u, 0u, 0u);
        *(uint4*)(xsp + tid*XS_RS + 256) = z;
    }
    __syncthreads();

    int warp = tid >> 5;
    int lane = tid & 31;
    int mblk = warp & 3;
    int nq   = warp >> 2;
    int gid = lane >> 2;
    int tig = lane & 3;

    float cacc[4][2][4];
#pragma unroll
    for (int mf = 0; mf < 4; mf++)
#pragma unroll
        for (int nf = 0; nf < 2; nf++)
#pragma unroll
            for (int q = 0; q < 4; q++) cacc[mf][nf][q] = 0.0f;

#pragma unroll
    for (int t9 = 0; t9 < 9; t9++) {
        int di = t9 / 3, dj = t9 % 3;
#pragma unroll
        for (int kh = 0; kh < 2; kh++) {
            uint32_t bfrag[2][2];
            const uint2* wp = g_wfragh + ((((t9*2 + kh)*4 + nq)*2)*32) + lane;
            {
                uint2 v0 = __ldg(wp);
                uint2 v1 = __ldg(wp + 32);
                bfrag[0][0] = v0.x; bfrag[0][1] = v0.y;
                bfrag[1][0] = v1.x; bfrag[1][1] = v1.y;
            }
            const uint32_t* xa = xsp + ((kh*8 + tig    )*3 + di)*XS_RS + dj;
            const uint32_t* xb = xsp + ((kh*8 + tig + 4)*3 + di)*XS_RS + dj;
#pragma unroll
            for (int mf = 0; mf < 4; mf++) {
                int j0 = mblk*64 + mf*16 + gid;
                uint32_t afrag[4];
                afrag[0] = xa[j0];
                afrag[1] = xa[j0 + 8];
                afrag[2] = xb[j0];
                afrag[3] = xb[j0 + 8];
                mma_bf16(cacc[mf][0], afrag, bfrag[0]);
                mma_bf16(cacc[mf][1], afrag, bfrag[1]);
            }
        }
    }

    /* epilogue: bias + relu + bf16 store to g_x1h[b][oc][i][j] */
#pragma unroll
    for (int nf = 0; nf < 2; nf++) {
        int oc = nq*16 + nf*8 + tig*2;
        float bias0 = __ldg(&b1[oc]);
        float bias1 = __ldg(&b1[oc+1]);
        __nv_bfloat16* o0 = g_x1h + (size_t)b*K_FC + (size_t)oc*(H1*W1) + (size_t)i*W1;
        __nv_bfloat16* o1 = o0 + H1*W1;
#pragma unroll
        for (int mf = 0; mf < 4; mf++) {
            int j = mblk*64 + mf*16 + gid;
            if (j < W1) {
                o0[j] = __float2bfloat16_rn(fmaxf(cacc[mf][nf][0] + bias0, 0.0f));
                o1[j] = __float2bfloat16_rn(fmaxf(cacc[mf][nf][1] + bias1, 0.0f));
            }
            if (j + 8 < W1) {
                o0[j+8] = __float2bfloat16_rn(fmaxf(cacc[mf][nf][2] + bias0, 0.0f));
                o1[j+8] = __float2bfloat16_rn(fmaxf(cacc[mf][nf][3] + bias1, 0.0f));
            }
        }
    }
}

/* ---------------- FC via bf16 tensor cores -------------------------------
 * D[f=40][b=32] = wr[40][K] * x1[32][K]^T, per block one KC=1152 chunk.
 * 9 k128-tiles; wr tile cvt->bf16 + x1 tile staged to smem, stride 68 u32
 * (frag LDS bank = 4*gid+tig: conflict-free). Warp w owns k16 slice w of
 * each tile: 3 m-tiles x 4 n-tiles = 12 MMA. fp32 acc; smem warp-reduce. */
__global__ void __launch_bounds__(256) fc_kernel(const float* __restrict__ wr) {
    __shared__ union {
        struct { uint32_t wrs[48*68]; uint32_t x1s[32*68]; } t;
        float red[8*FREQ*BB];
    } sm;
    int chunk = blockIdx.x;
    int tid   = threadIdx.x;
    int warp  = tid >> 5;
    int lane  = tid & 31;
    int gid   = lane >> 2;
    int tig   = lane & 3;

    float acc[3][4][4];
#pragma unroll
    for (int mt = 0; mt < 3; mt++)
#pragma unroll
        for (int nt = 0; nt < 4; nt++)
#pragma unroll
            for (int q = 0; q < 4; q++) acc[mt][nt][q] = 0.0f;

    for (int tile = 0; tile < 9; tile++) {
        int k0 = chunk*KC + tile*128;
        /* stage wr tile (fp32 -> bf16x2), rows 40..47 zero */
#pragma unroll
        for (int s = 0; s < 12; s++) {
            int idx = tid + s*256;
            int row = idx >> 6, c = idx & 63;
            uint32_t v = 0u;
            if (row < FREQ) {
                float2 f2 = *(const float2*)(wr + (size_t)row*K_FC + k0 + 2*c);
                v = packbf2(f2.x, f2.y);
            }
            sm.t.wrs[row*68 + c] = v;
        }
        /* stage x1 tile (already bf16 pairs) */
#pragma unroll
        for (int s = 0; s < 8; s++) {
            int idx = tid + s*256;
            int row = idx >> 6, c = idx & 63;
            sm.t.x1s[row*68 + c] =
                *(const uint32_t*)(g_x1h + (size_t)row*K_FC + k0 + 2*c);
        }
        __syncthreads();

        int ko = warp*8 + tig;
        uint32_t bfrag[4][2];
#pragma unroll
        for (int nt = 0; nt < 4; nt++) {
            bfrag[nt][0] = sm.t.x1s[(nt*8 + gid)*68 + ko];
            bfrag[nt][1] = sm.t.x1s[(nt*8 + gid)*68 + ko + 4];
        }
#pragma unroll
        for (int mt = 0; mt < 3; mt++) {
            uint32_t afrag[4];
            afrag[0] = sm.t.wrs[(mt*16 + gid    )*68 + ko];
            afrag[1] = sm.t.wrs[(mt*16 + gid + 8)*68 + ko];
            afrag[2] = sm.t.wrs[(mt*16 + gid    )*68 + ko + 4];
            afrag[3] = sm.t.wrs[(mt*16 + gid + 8)*68 + ko + 4];
#pragma unroll
            for (int nt = 0; nt < 4; nt++)
                mma_bf16(acc[mt][nt], afrag, bfrag[nt]);
        }
        __syncthreads();
    }

    /* per-warp results -> red[warp][f*32+b]; rows f>=40 dropped */
#pragma unroll
    for (int mt = 0; mt < 3; mt++)
#pragma unroll
        for (int nt = 0; nt < 4; nt++) {
            int f0 = mt*16 + gid;
            int b0 = nt*8 + 2*tig;
            float* rp = sm.red + warp*(FREQ*BB);
            if (f0 < FREQ) {
                rp[f0*BB + b0]     = acc[mt][nt][0];
                rp[f0*BB + b0 + 1] = acc[mt][nt][1];
            }
            if (f0 + 8 < FREQ) {
                rp[(f0+8)*BB + b0]     = acc[mt][nt][2];
                rp[(f0+8)*BB + b0 + 1] = acc[mt][nt][3];
            }
        }
    __syncthreads();
    for (int p = tid; p < FREQ*BB; p += 256) {
        float s = 0.0f;
#pragma unroll
        for (int w = 0; w < 8; w++) s += sm.red[w*(FREQ*BB) + p];
        g_gpart[(size_t)chunk*(FREQ*BB) + p] = s;
    }
}

/* ---------------- reduce partials + bias + sigmoid ------------------------ */
__global__ void gate_kernel(const float* __restrict__ br) {
    int p = blockIdx.x*blockDim.x + threadIdx.x;  /* p = f*32 + b */
    if (p >= FREQ*BB) return;
    float s = 0.0f;
    for (int c = 0; c < NCHUNK; c++) s += g_gpart[c*(FREQ*BB) + p];
    int f = p >> 5;
    int b = p & 31;
    s += __ldg(&br[f]);
    g_gates[b*FREQ + f] = 1.0f / (1.0f + expf(-s));
}

/* ---------------- weighted mean of gates --------------------------------- */
__global__ void wtd_kernel(float* __restrict__ out, int out_size) {
    __shared__ float red[256];
    int tid = threadIdx.x;
    float s = 0.0f;
    for (int i = tid; i < BB*FREQ; i += 256) {
        int f = i % FREQ;
        s += g_gates[i] * (2.0f * (float)(f+1));
    }
    red[tid] = s;
    __syncthreads();
    for (int o = 128; o > 0; o >>= 1) {
        if (tid < o) red[tid] += red[tid + o];
        __syncthreads();
    }
    if (tid == 0) out[out_size - 1] = red[0] / (float)(BB*FREQ);
}

/* ---------------- projection (trig fused): grid (b, f), 128 thr ---------- */
__global__ void proj_kernel(float* __restrict__ out) {
    __shared__ float sp[WW];
    __shared__ float cp[WW];
    int b = blockIdx.x;
    int f = blockIdx.y;
    int tid  = threadIdx.x;
    int warp = tid >> 5;
    int lane = tid & 31;

    float fs = 2.0f * (float)(f+1);
#pragma unroll
    for (int q = 0; q < 2; q++) {
        int w = tid + q*128;
        float t  = (0.5f/255.0f) * (float)w;
        float ph = TWO_PI * fs * t;
        float sv, cv;
        sincosf(ph, &sv, &cv);
        sp[w] = sv;
        cp[w] = cv;
    }
    __syncthreads();

    float gate = g_gates[b*FREQ + f];
    for (int h = warp; h < HH; h += 4) {
        const float* xp = g_feats + ((size_t)b*HH + h)*WW;
        float s = 0.0f, c = 0.0f;
#pragma unroll
        for (int q = 0; q < 8; q++) {
            int w = lane + q*32;
            float v = xp[w];
            s += sp[w]*v;
            c += cp[w]*v;
        }
#pragma unroll
        for (int o = 16; o > 0; o >>= 1) {
            s += __shfl_xor_sync(0xffffffffu, s, o);
            c += __shfl_xor_sync(0xffffffffu, c, o);
        }
        if (lane == 0) {
            s *= (1.0f/(float)WW);
            c *= (1.0f/(float)WW);
            out[(size_t)b*(FREQ*HH) + f*HH + h] = sqrtf(s*s + c*c) * gate;
        }
    }
}

/* ---------------- launch -------------------------------------------------- */
extern "C" void kernel_launch(void* const* d_in, const int* in_sizes, int n_in,
                              void* d_out, int out_size) {
    const float* in = (const float*)d_in[0];
    const float* w0 = (const float*)d_in[1];
    const float* b0 = (const float*)d_in[2];
    const float* w1 = (const float*)d_in[3];
    const float* b1 = (const float*)d_in[4];
    const float* wf = (const float*)d_in[5];
    const float* bf = (const float*)d_in[6];
    const float* wr = (const float*)d_in[7];
    const float* br = (const float*)d_in[8];
    float* out = (float*)d_out;

    cudaFuncSetAttribute(conv1_mma_kernel,
                         cudaFuncAttributeMaxDynamicSharedMemorySize, SM_TOT);

    wprep_kernel<<<18, 256>>>(w1);
    conv0_kernel<<<(BB*16*H0*64)/256, 256>>>(in, w0, b0);
    feats_kernel<<<(BB*HH*WW + 255)/256, 256>>>(in, wf, bf);
    conv1_mma_kernel<<<dim3(H1, BB), 512, SM_TOT>>>(b1);
    fc_kernel<<<NCHUNK, 256>>>(wr);
    gate_kernel<<<(FREQ*BB + 255)/256, 256>>>(br);
    wtd_kernel<<<1, 256>>>(out, out_size);
    proj_kernel<<<dim3(BB, FREQ), 128>>>(out);
}

// round 7
// speedup vs baseline: 3.3994x; 1.0956x over previous
#include <cuda_runtime.h>
#include <cuda_bf16.h>
#include <math.h>
#include <stdint.h>

#define BB   32
#define HH   40
#define WW   256
#define FREQ 40
#define C0   32
#define H0   38
#define C1   64
#define H1   36
#define W1   252
#define K_FC (C1*H1*W1)          /* 580608 */
#define FC_TILES 6
#define FC_KC (FC_TILES*128)     /* 768 */
#define NCHUNK 756               /* K_FC / FC_KC */
#define TWO_PI 6.28318530717958647692f

/* ---------------- scratch (device globals) ------------------------------- */
/* x0 packed: [b][icp(16)][i(38)][j(256)] u32 = bf16x2 (ic even lo, odd hi) */
__device__ uint32_t      g_x0p[(size_t)BB*16*H0*256];
__device__ __nv_bfloat16 g_x1h[(size_t)BB*K_FC];      /* conv1 out, bf16   */
__device__ uint2         g_wfragh[9*2*4*2*32];        /* w1 bf16 frag order */
__device__ float         g_feats[BB*HH*WW];
__device__ float         g_gpart[NCHUNK*FREQ*BB];
__device__ float         g_gates[BB*FREQ];

/* ---------------- helpers ------------------------------------------------- */
__device__ __forceinline__ uint32_t packbf2(float lo, float hi) {
    __nv_bfloat162 h = __floats2bfloat162_rn(lo, hi);
    return *(uint32_t*)&h;
}

__device__ __forceinline__ void mma_bf16(float c[4], const uint32_t a[4],
                                         const uint32_t b[2]) {
    asm volatile(
        "mma.sync.aligned.m16n8k16.row.col.f32.bf16.bf16.f32 "
        "{%0,%1,%2,%3}, {%4,%5,%6,%7}, {%8,%9}, {%0,%1,%2,%3};"
        : "+f"(c[0]), "+f"(c[1]), "+f"(c[2]), "+f"(c[3])
        : "r"(a[0]), "r"(a[1]), "r"(a[2]), "r"(a[3]), "r"(b[0]), "r"(b[1]));
}

/* ---------------- fused prep: conv0 + feats + wprep ----------------------
 * blocks [0,4864): conv0;  [4864,6144): feats;  [6144,6162): wprep */
__global__ void prep_kernel(const float* __restrict__ in,
                            const float* __restrict__ w0,
                            const float* __restrict__ b0,
                            const float* __restrict__ wf,
                            const float* __restrict__ bf,
                            const float* __restrict__ w1) {
    int bid = blockIdx.x;
    if (bid < 4864) {
        /* conv0: 1->32ch 3x3 VALID + bias + relu, bf16x2-packed output */
        int idx = bid*256 + threadIdx.x;
        int jg = idx & 63;
        int t  = idx >> 6;
        int i  = t % H0;  t /= H0;
        int op = t % 16;  t /= 16;
        int b  = t;
        int j0 = jg*4;
        int oc0 = op*2;

        float wA[9], wB[9];
#pragma unroll
        for (int q = 0; q < 9; q++) {
            wA[q] = __ldg(&w0[oc0*9+q]);
            wB[q] = __ldg(&w0[(oc0+1)*9+q]);
        }
        float biasA = __ldg(&b0[oc0]);
        float biasB = __ldg(&b0[oc0+1]);
        float aA[4] = {biasA, biasA, biasA, biasA};
        float aB[4] = {biasB, biasB, biasB, biasB};

        const float* ip = in + (size_t)b*HH*WW;
#pragma unroll
        for (int di = 0; di < 3; di++) {
            const float* row = ip + (i+di)*WW;
            float x[6];
#pragma unroll
            for (int c = 0; c < 6; c++) x[c] = (j0+c < WW) ? row[j0+c] : 0.0f;
#pragma unroll
            for (int dj = 0; dj < 3; dj++) {
                float wa = wA[di*3+dj], wb = wB[di*3+dj];
#pragma unroll
                for (int q = 0; q < 4; q++) {
                    aA[q] += wa * x[q+dj];
                    aB[q] += wb * x[q+dj];
                }
            }
        }
        uint4 v;
        uint32_t* vp = &v.x;
#pragma unroll
        for (int q = 0; q < 4; q++) {
            bool ok = (j0+q < 254);
            vp[q] = packbf2(ok ? fmaxf(aA[q], 0.0f) : 0.0f,
                            ok ? fmaxf(aB[q], 0.0f) : 0.0f);
        }
        *(uint4*)(g_x0p + (((size_t)b*16 + op)*H0 + i)*256 + j0) = v;
    } else if (bid < 6144) {
        /* feats: 5-tap conv along W, zero pad, + bias */
        int idx = (bid - 4864)*256 + threadIdx.x;
        int w = idx & (WW-1);
        const float* row = in + (idx - w);
        float acc = __ldg(&bf[0]);
#pragma unroll
        for (int t = 0; t < 5; t++) {
            int ww = w + t - 2;
            if (ww >= 0 && ww < WW) acc += __ldg(&wf[t]) * row[ww];
        }
        g_feats[idx] = acc;
    } else {
        /* wprep: w1 -> bf16 fragment layout [t9][kh][nq][nf][lane] */
        int t = (bid - 6144)*256 + threadIdx.x;
        int lane = t & 31;
        int nf   = (t >> 5) & 1;
        int nq   = (t >> 6) & 3;
        int kh   = (t >> 8) & 1;
        int t9   = t >> 9;
        int gid = lane >> 2, tig = lane & 3;
        int oc  = nq*16 + nf*8 + gid;
        int ic0 = 2*tig + 16*kh;
        uint2 v;
        v.x = packbf2(__ldg(&w1[oc*288 + (ic0  )*9 + t9]),
                      __ldg(&w1[oc*288 + (ic0+1)*9 + t9]));
        v.y = packbf2(__ldg(&w1[oc*288 + (ic0+8)*9 + t9]),
                      __ldg(&w1[oc*288 + (ic0+9)*9 + t9]));
        g_wfragh[t] = v;
    }
}

/* ---------------- conv1 via bf16 m16n8k16, 2 output rows per CTA ---------
 * Block (i2, b): rows i = 2*i2, 2*i2+1.  1024 thr = 32 warps:
 * warp = nq(4) x mblk(4) x rsel(2).  xsp: [icp(16)][dr(4)][258] u32 bf16x2.
 * 4*258 = 1032 == 8 (mod 32): frag LDS banks = 8*tig + gid, conflict-free. */
#define XR    258
#define SM1   (64*XR*4)          /* 66048 bytes */

__global__ void __launch_bounds__(1024, 1)
conv1_mma_kernel(const float* __restrict__ b1) {
    extern __shared__ uint32_t xsp[];

    int i2  = blockIdx.x;
    int b   = blockIdx.y;
    int tid = threadIdx.x;

    /* stage 4 input rows x 16 icp (uint2 = 8B, rows 2*i2 .. 2*i2+3) */
    for (int t = tid; t < 64*128; t += 1024) {
        int c2 = t & 127;
        int r  = t >> 7;            /* r = icp*4 + dr */
        int dr = r & 3;
        int ic = r >> 2;
        uint2 v = *(const uint2*)(g_x0p +
            (((size_t)b*16 + ic)*H0 + (2*i2 + dr))*256 + c2*2);
        *(uint2*)(xsp + r*XR + c2*2) = v;
    }
    if (tid < 128) xsp[(tid >> 1)*XR + 256 + (tid & 1)] = 0u;
    __syncthreads();

    int warp = tid >> 5;
    int lane = tid & 31;
    int nq   = warp & 3;
    int mblk = (warp >> 2) & 3;
    int rsel = warp >> 4;
    int gid  = lane >> 2;
    int tig  = lane & 3;

    float cacc[4][2][4];
#pragma unroll
    for (int mf = 0; mf < 4; mf++)
#pragma unroll
        for (int nf = 0; nf < 2; nf++)
#pragma unroll
            for (int q = 0; q < 4; q++) cacc[mf][nf][q] = 0.0f;

#pragma unroll
    for (int t9 = 0; t9 < 9; t9++) {
        int di = t9 / 3, dj = t9 % 3;
        int dr = di + rsel;
#pragma unroll
        for (int kh = 0; kh < 2; kh++) {
            uint32_t bfrag[2][2];
            const uint2* wp = g_wfragh + ((((t9*2 + kh)*4 + nq)*2)*32) + lane;
            {
                uint2 v0 = __ldg(wp);
                uint2 v1 = __ldg(wp + 32);
                bfrag[0][0] = v0.x; bfrag[0][1] = v0.y;
                bfrag[1][0] = v1.x; bfrag[1][1] = v1.y;
            }
            const uint32_t* xa = xsp + ((kh*8 + tig    )*4 + dr)*XR + dj;
            const uint32_t* xb = xsp + ((kh*8 + tig + 4)*4 + dr)*XR + dj;
#pragma unroll
            for (int mf = 0; mf < 4; mf++) {
                int j0 = mblk*64 + mf*16 + gid;
                uint32_t afrag[4];
                afrag[0] = xa[j0];
                afrag[1] = xa[j0 + 8];
                afrag[2] = xb[j0];
                afrag[3] = xb[j0 + 8];
                mma_bf16(cacc[mf][0], afrag, bfrag[0]);
                mma_bf16(cacc[mf][1], afrag, bfrag[1]);
            }
        }
    }

    /* epilogue: bias + relu + bf16 store to g_x1h[b][oc][i][j] */
    int i = 2*i2 + rsel;
#pragma unroll
    for (int nf = 0; nf < 2; nf++) {
        int oc = nq*16 + nf*8 + tig*2;
        float bias0 = __ldg(&b1[oc]);
        float bias1 = __ldg(&b1[oc+1]);
        __nv_bfloat16* o0 = g_x1h + (size_t)b*K_FC + (size_t)oc*(H1*W1) + (size_t)i*W1;
        __nv_bfloat16* o1 = o0 + H1*W1;
#pragma unroll
        for (int mf = 0; mf < 4; mf++) {
            int j = mblk*64 + mf*16 + gid;
            if (j < W1) {
                o0[j] = __float2bfloat16_rn(fmaxf(cacc[mf][nf][0] + bias0, 0.0f));
                o1[j] = __float2bfloat16_rn(fmaxf(cacc[mf][nf][1] + bias1, 0.0f));
            }
            if (j + 8 < W1) {
                o0[j+8] = __float2bfloat16_rn(fmaxf(cacc[mf][nf][2] + bias0, 0.0f));
                o1[j+8] = __float2bfloat16_rn(fmaxf(cacc[mf][nf][3] + bias1, 0.0f));
            }
        }
    }
}

/* ---------------- FC via bf16 tensor cores, register double-buffered -----
 * D[f=40][b=32] = wr[40][K] * x1[32][K]^T; 756 blocks x 6 k128-tiles.
 * Prefetch tile t+1 into regs while computing tile t from smem. */
__global__ void __launch_bounds__(256) fc_kernel(const float* __restrict__ wr) {
    __shared__ union {
        struct { uint32_t wrs[48*68]; uint32_t x1s[32*68]; } t;
        float red[8*FREQ*BB];
    } sm;
    int chunk = blockIdx.x;
    int tid   = threadIdx.x;
    int warp  = tid >> 5;
    int lane  = tid & 31;
    int gid   = lane >> 2;
    int tig   = lane & 3;

    /* wrs rows 40..47 stay zero for all tiles */
    for (int s = tid; s < 8*68; s += 256) sm.t.wrs[40*68 + s] = 0u;

    float acc[3][4][4];
#pragma unroll
    for (int mt = 0; mt < 3; mt++)
#pragma unroll
        for (int nt = 0; nt < 4; nt++)
#pragma unroll
            for (int q = 0; q < 4; q++) acc[mt][nt][q] = 0.0f;

    const float4* wr4 = (const float4*)wr;
    float4 wbuf[5];
    uint4  xbuf[2];

    /* prefetch tile 0 */
    {
        int k0 = chunk*FC_KC;
#pragma unroll
        for (int s = 0; s < 5; s++) {
            int idx = tid + s*256;
            int r = idx >> 5, cc = idx & 31;
            wbuf[s] = wr4[(size_t)r*(K_FC/4) + (k0 >> 2) + cc];
        }
#pragma unroll
        for (int s = 0; s < 2; s++) {
            int idx = tid + s*256;
            int r = idx >> 4, cc = idx & 15;
            xbuf[s] = *(const uint4*)(g_x1h + (size_t)r*K_FC + k0 + cc*8);
        }
    }

    for (int tile = 0; tile < FC_TILES; tile++) {
        /* commit prefetched tile to smem */
#pragma unroll
        for (int s = 0; s < 5; s++) {
            int idx = tid + s*256;
            int r = idx >> 5, cc = idx & 31;
            sm.t.wrs[r*68 + 2*cc]     = packbf2(wbuf[s].x, wbuf[s].y);
            sm.t.wrs[r*68 + 2*cc + 1] = packbf2(wbuf[s].z, wbuf[s].w);
        }
#pragma unroll
        for (int s = 0; s < 2; s++) {
            int idx = tid + s*256;
            int r = idx >> 4, cc = idx & 15;
            *(uint4*)&sm.t.x1s[r*68 + cc*4] = xbuf[s];
        }
        __syncthreads();

        /* prefetch next tile while computing this one */
        if (tile + 1 < FC_TILES) {
            int k0 = chunk*FC_KC + (tile+1)*128;
#pragma unroll
            for (int s = 0; s < 5; s++) {
                int idx = tid + s*256;
                int r = idx >> 5, cc = idx & 31;
                wbuf[s] = wr4[(size_t)r*(K_FC/4) + (k0 >> 2) + cc];
            }
#pragma unroll
            for (int s = 0; s < 2; s++) {
                int idx = tid + s*256;
                int r = idx >> 4, cc = idx & 15;
                xbuf[s] = *(const uint4*)(g_x1h + (size_t)r*K_FC + k0 + cc*8);
            }
        }

        int ko = warp*8 + tig;
        uint32_t bfrag[4][2];
#pragma unroll
        for (int nt = 0; nt < 4; nt++) {
            bfrag[nt][0] = sm.t.x1s[(nt*8 + gid)*68 + ko];
            bfrag[nt][1] = sm.t.x1s[(nt*8 + gid)*68 + ko + 4];
        }
#pragma unroll
        for (int mt = 0; mt < 3; mt++) {
            uint32_t afrag[4];
            afrag[0] = sm.t.wrs[(mt*16 + gid    )*68 + ko];
            afrag[1] = sm.t.wrs[(mt*16 + gid + 8)*68 + ko];
            afrag[2] = sm.t.wrs[(mt*16 + gid    )*68 + ko + 4];
            afrag[3] = sm.t.wrs[(mt*16 + gid + 8)*68 + ko + 4];
#pragma unroll
            for (int nt = 0; nt < 4; nt++)
                mma_bf16(acc[mt][nt], afrag, bfrag[nt]);
        }
        __syncthreads();
    }

    /* per-warp results -> red[warp][f*32+b]; rows f>=40 dropped */
#pragma unroll
    for (int mt = 0; mt < 3; mt++)
#pragma unroll
        for (int nt = 0; nt < 4; nt++) {
            int f0 = mt*16 + gid;
            int b0 = nt*8 + 2*tig;
            float* rp = sm.red + warp*(FREQ*BB);
            if (f0 < FREQ) {
                rp[f0*BB + b0]     = acc[mt][nt][0];
                rp[f0*BB + b0 + 1] = acc[mt][nt][1];
            }
            if (f0 + 8 < FREQ) {
                rp[(f0+8)*BB + b0]     = acc[mt][nt][2];
                rp[(f0+8)*BB + b0 + 1] = acc[mt][nt][3];
            }
        }
    __syncthreads();
    for (int p = tid; p < FREQ*BB; p += 256) {
        float s = 0.0f;
#pragma unroll
        for (int w = 0; w < 8; w++) s += sm.red[w*(FREQ*BB) + p];
        g_gpart[(size_t)chunk*(FREQ*BB) + p] = s;
    }
}

/* ---------------- reduce partials + bias + sigmoid ------------------------ */
__global__ void gate_kernel(const float* __restrict__ br) {
    int p = blockIdx.x*blockDim.x + threadIdx.x;  /* p = f*32 + b */
    if (p >= FREQ*BB) return;
    float s = 0.0f;
#pragma unroll 4
    for (int c = 0; c < NCHUNK; c++) s += g_gpart[c*(FREQ*BB) + p];
    int f = p >> 5;
    int b = p & 31;
    s += __ldg(&br[f]);
    g_gates[b*FREQ + f] = 1.0f / (1.0f + expf(-s));
}

/* ---------------- weighted mean of gates --------------------------------- */
__global__ void wtd_kernel(float* __restrict__ out, int out_size) {
    __shared__ float red[256];
    int tid = threadIdx.x;
    float s = 0.0f;
    for (int i = tid; i < BB*FREQ; i += 256) {
        int f = i % FREQ;
        s += g_gates[i] * (2.0f * (float)(f+1));
    }
    red[tid] = s;
    __syncthreads();
    for (int o = 128; o > 0; o >>= 1) {
        if (tid < o) red[tid] += red[tid + o];
        __syncthreads();
    }
    if (tid == 0) out[out_size - 1] = red[0] / (float)(BB*FREQ);
}

/* ---------------- projection (trig fused): grid (b, f), 128 thr ---------- */
__global__ void proj_kernel(float* __restrict__ out) {
    __shared__ float sp[WW];
    __shared__ float cp[WW];
    int b = blockIdx.x;
    int f = blockIdx.y;
    int tid  = threadIdx.x;
    int warp = tid >> 5;
    int lane = tid & 31;

    float fs = 2.0f * (float)(f+1);
#pragma unroll
    for (int q = 0; q < 2; q++) {
        int w = tid + q*128;
        float t  = (0.5f/255.0f) * (float)w;
        float ph = TWO_PI * fs * t;
        float sv, cv;
        sincosf(ph, &sv, &cv);
        sp[w] = sv;
        cp[w] = cv;
    }
    __syncthreads();

    float gate = g_gates[b*FREQ + f];
    for (int h = warp; h < HH; h += 4) {
        const float* xp = g_feats + ((size_t)b*HH + h)*WW;
        float s = 0.0f, c = 0.0f;
#pragma unroll
        for (int q = 0; q < 8; q++) {
            int w = lane + q*32;
            float v = xp[w];
            s += sp[w]*v;
            c += cp[w]*v;
        }
#pragma unroll
        for (int o = 16; o > 0; o >>= 1) {
            s += __shfl_xor_sync(0xffffffffu, s, o);
            c += __shfl_xor_sync(0xffffffffu, c, o);
        }
        if (lane == 0) {
            s *= (1.0f/(float)WW);
            c *= (1.0f/(float)WW);
            out[(size_t)b*(FREQ*HH) + f*HH + h] = sqrtf(s*s + c*c) * gate;
        }
    }
}

/* ---------------- launch -------------------------------------------------- */
extern "C" void kernel_launch(void* const* d_in, const int* in_sizes, int n_in,
                              void* d_out, int out_size) {
    const float* in = (const float*)d_in[0];
    const float* w0 = (const float*)d_in[1];
    const float* b0 = (const float*)d_in[2];
    const float* w1 = (const float*)d_in[3];
    const float* b1 = (const float*)d_in[4];
    const float* wf = (const float*)d_in[5];
    const float* bf = (const float*)d_in[6];
    const float* wr = (const float*)d_in[7];
    const float* br = (const float*)d_in[8];
    float* out = (float*)d_out;

    cudaFuncSetAttribute(conv1_mma_kernel,
                         cudaFuncAttributeMaxDynamicSharedMemorySize, SM1);

    prep_kernel<<<6162, 256>>>(in, w0, b0, wf, bf, w1);
    conv1_mma_kernel<<<dim3(18, BB), 1024, SM1>>>(b1);
    fc_kernel<<<NCHUNK, 256>>>(wr);
    gate_kernel<<<(FREQ*BB + 255)/256, 256>>>(br);
    wtd_kernel<<<1, 256>>>(out, out_size);
    proj_kernel<<<dim3(BB, FREQ), 128>>>(out);
}

// round 8
// speedup vs baseline: 3.7078x; 1.0907x over previous
#include <cuda_runtime.h>
#include <cuda_bf16.h>
#include <math.h>
#include <stdint.h>

#define BB   32
#define HH   40
#define WW   256
#define FREQ 40
#define C0   32
#define H0   38
#define C1   64
#define H1   36
#define W1   252
#define K_FC (C1*H1*W1)          /* 580608 */
#define FC_TILES 6
#define FC_KC (FC_TILES*128)     /* 768 */
#define NCHUNK 756               /* K_FC / FC_KC */
#define TWO_PI 6.28318530717958647692f

/* ---------------- scratch (device globals) ------------------------------- */
/* x0 packed: [b][icp(16)][i(38)][j(256)] u32 = bf16x2 (ic even lo, odd hi) */
__device__ uint32_t      g_x0p[(size_t)BB*16*H0*256];
__device__ __nv_bfloat16 g_x1h[(size_t)BB*K_FC];      /* conv1 out, bf16   */
__device__ uint2         g_wfragh[9*2*4*2*32];        /* w1 bf16 frag order */
__device__ float         g_feats[BB*HH*WW];
__device__ float         g_gpart[(size_t)FREQ*BB*NCHUNK];  /* [p][chunk] */
__device__ float         g_gates[BB*FREQ];

/* ---------------- helpers ------------------------------------------------- */
__device__ __forceinline__ uint32_t packbf2(float lo, float hi) {
    __nv_bfloat162 h = __floats2bfloat162_rn(lo, hi);
    return *(uint32_t*)&h;
}

__device__ __forceinline__ void mma_bf16(float c[4], const uint32_t a[4],
                                         const uint32_t b[2]) {
    asm volatile(
        "mma.sync.aligned.m16n8k16.row.col.f32.bf16.bf16.f32 "
        "{%0,%1,%2,%3}, {%4,%5,%6,%7}, {%8,%9}, {%0,%1,%2,%3};"
        : "+f"(c[0]), "+f"(c[1]), "+f"(c[2]), "+f"(c[3])
        : "r"(a[0]), "r"(a[1]), "r"(a[2]), "r"(a[3]), "r"(b[0]), "r"(b[1]));
}

/* ---------------- fused prep: conv0 + feats + wprep ----------------------
 * blocks [0,4864): conv0;  [4864,6144): feats;  [6144,6162): wprep */
__global__ void prep_kernel(const float* __restrict__ in,
                            const float* __restrict__ w0,
                            const float* __restrict__ b0,
                            const float* __restrict__ wf,
                            const float* __restrict__ bf,
                            const float* __restrict__ w1) {
    int bid = blockIdx.x;
    if (bid < 4864) {
        /* conv0: 1->32ch 3x3 VALID + bias + relu, bf16x2-packed output */
        int idx = bid*256 + threadIdx.x;
        int jg = idx & 63;
        int t  = idx >> 6;
        int i  = t % H0;  t /= H0;
        int op = t % 16;  t /= 16;
        int b  = t;
        int j0 = jg*4;
        int oc0 = op*2;

        float wA[9], wB[9];
#pragma unroll
        for (int q = 0; q < 9; q++) {
            wA[q] = __ldg(&w0[oc0*9+q]);
            wB[q] = __ldg(&w0[(oc0+1)*9+q]);
        }
        float biasA = __ldg(&b0[oc0]);
        float biasB = __ldg(&b0[oc0+1]);
        float aA[4] = {biasA, biasA, biasA, biasA};
        float aB[4] = {biasB, biasB, biasB, biasB};

        const float* ip = in + (size_t)b*HH*WW;
#pragma unroll
        for (int di = 0; di < 3; di++) {
            const float* row = ip + (i+di)*WW;
            float x[6];
#pragma unroll
            for (int c = 0; c < 6; c++) x[c] = (j0+c < WW) ? row[j0+c] : 0.0f;
#pragma unroll
            for (int dj = 0; dj < 3; dj++) {
                float wa = wA[di*3+dj], wb = wB[di*3+dj];
#pragma unroll
                for (int q = 0; q < 4; q++) {
                    aA[q] += wa * x[q+dj];
                    aB[q] += wb * x[q+dj];
                }
            }
        }
        uint4 v;
        uint32_t* vp = &v.x;
#pragma unroll
        for (int q = 0; q < 4; q++) {
            bool ok = (j0+q < 254);
            vp[q] = packbf2(ok ? fmaxf(aA[q], 0.0f) : 0.0f,
                            ok ? fmaxf(aB[q], 0.0f) : 0.0f);
        }
        *(uint4*)(g_x0p + (((size_t)b*16 + op)*H0 + i)*256 + j0) = v;
    } else if (bid < 6144) {
        /* feats: 5-tap conv along W, zero pad, + bias */
        int idx = (bid - 4864)*256 + threadIdx.x;
        int w = idx & (WW-1);
        const float* row = in + (idx - w);
        float acc = __ldg(&bf[0]);
#pragma unroll
        for (int t = 0; t < 5; t++) {
            int ww = w + t - 2;
            if (ww >= 0 && ww < WW) acc += __ldg(&wf[t]) * row[ww];
        }
        g_feats[idx] = acc;
    } else {
        /* wprep: w1 -> bf16 fragment layout [t9][kh][nq][nf][lane] */
        int t = (bid - 6144)*256 + threadIdx.x;
        int lane = t & 31;
        int nf   = (t >> 5) & 1;
        int nq   = (t >> 6) & 3;
        int kh   = (t >> 8) & 1;
        int t9   = t >> 9;
        int gid = lane >> 2, tig = lane & 3;
        int oc  = nq*16 + nf*8 + gid;
        int ic0 = 2*tig + 16*kh;
        uint2 v;
        v.x = packbf2(__ldg(&w1[oc*288 + (ic0  )*9 + t9]),
                      __ldg(&w1[oc*288 + (ic0+1)*9 + t9]));
        v.y = packbf2(__ldg(&w1[oc*288 + (ic0+8)*9 + t9]),
                      __ldg(&w1[oc*288 + (ic0+9)*9 + t9]));
        g_wfragh[t] = v;
    }
}

/* ---------------- conv1 via bf16 m16n8k16, 2 output rows per CTA --------- */
#define XR    258
#define SM1   (64*XR*4)          /* 66048 bytes */

__global__ void __launch_bounds__(1024, 1)
conv1_mma_kernel(const float* __restrict__ b1) {
    extern __shared__ uint32_t xsp[];

    int i2  = blockIdx.x;
    int b   = blockIdx.y;
    int tid = threadIdx.x;

    /* stage 4 input rows x 16 icp (uint2 = 8B, rows 2*i2 .. 2*i2+3) */
    for (int t = tid; t < 64*128; t += 1024) {
        int c2 = t & 127;
        int r  = t >> 7;            /* r = icp*4 + dr */
        int dr = r & 3;
        int ic = r >> 2;
        uint2 v = *(const uint2*)(g_x0p +
            (((size_t)b*16 + ic)*H0 + (2*i2 + dr))*256 + c2*2);
        *(uint2*)(xsp + r*XR + c2*2) = v;
    }
    if (tid < 128) xsp[(tid >> 1)*XR + 256 + (tid & 1)] = 0u;
    __syncthreads();

    int warp = tid >> 5;
    int lane = tid & 31;
    int nq   = warp & 3;
    int mblk = (warp >> 2) & 3;
    int rsel = warp >> 4;
    int gid  = lane >> 2;
    int tig  = lane & 3;

    float cacc[4][2][4];
#pragma unroll
    for (int mf = 0; mf < 4; mf++)
#pragma unroll
        for (int nf = 0; nf < 2; nf++)
#pragma unroll
            for (int q = 0; q < 4; q++) cacc[mf][nf][q] = 0.0f;

#pragma unroll
    for (int t9 = 0; t9 < 9; t9++) {
        int di = t9 / 3, dj = t9 % 3;
        int dr = di + rsel;
#pragma unroll
        for (int kh = 0; kh < 2; kh++) {
            uint32_t bfrag[2][2];
            const uint2* wp = g_wfragh + ((((t9*2 + kh)*4 + nq)*2)*32) + lane;
            {
                uint2 v0 = __ldg(wp);
                uint2 v1 = __ldg(wp + 32);
                bfrag[0][0] = v0.x; bfrag[0][1] = v0.y;
                bfrag[1][0] = v1.x; bfrag[1][1] = v1.y;
            }
            const uint32_t* xa = xsp + ((kh*8 + tig    )*4 + dr)*XR + dj;
            const uint32_t* xb = xsp + ((kh*8 + tig + 4)*4 + dr)*XR + dj;
#pragma unroll
            for (int mf = 0; mf < 4; mf++) {
                int j0 = mblk*64 + mf*16 + gid;
                uint32_t afrag[4];
                afrag[0] = xa[j0];
                afrag[1] = xa[j0 + 8];
                afrag[2] = xb[j0];
                afrag[3] = xb[j0 + 8];
                mma_bf16(cacc[mf][0], afrag, bfrag[0]);
                mma_bf16(cacc[mf][1], afrag, bfrag[1]);
            }
        }
    }

    /* epilogue: bias + relu + bf16 store to g_x1h[b][oc][i][j] */
    int i = 2*i2 + rsel;
#pragma unroll
    for (int nf = 0; nf < 2; nf++) {
        int oc = nq*16 + nf*8 + tig*2;
        float bias0 = __ldg(&b1[oc]);
        float bias1 = __ldg(&b1[oc+1]);
        __nv_bfloat16* o0 = g_x1h + (size_t)b*K_FC + (size_t)oc*(H1*W1) + (size_t)i*W1;
        __nv_bfloat16* o1 = o0 + H1*W1;
#pragma unroll
        for (int mf = 0; mf < 4; mf++) {
            int j = mblk*64 + mf*16 + gid;
            if (j < W1) {
                o0[j] = __float2bfloat16_rn(fmaxf(cacc[mf][nf][0] + bias0, 0.0f));
                o1[j] = __float2bfloat16_rn(fmaxf(cacc[mf][nf][1] + bias1, 0.0f));
            }
            if (j + 8 < W1) {
                o0[j+8] = __float2bfloat16_rn(fmaxf(cacc[mf][nf][2] + bias0, 0.0f));
                o1[j+8] = __float2bfloat16_rn(fmaxf(cacc[mf][nf][3] + bias1, 0.0f));
            }
        }
    }
}

/* ---------------- FC via bf16 tensor cores, register double-buffered ----- */
__global__ void __launch_bounds__(256) fc_kernel(const float* __restrict__ wr) {
    __shared__ union {
        struct { uint32_t wrs[48*68]; uint32_t x1s[32*68]; } t;
        float red[8*FREQ*BB];
    } sm;
    int chunk = blockIdx.x;
    int tid   = threadIdx.x;
    int warp  = tid >> 5;
    int lane  = tid & 31;
    int gid   = lane >> 2;
    int tig   = lane & 3;

    /* wrs rows 40..47 stay zero for all tiles */
    for (int s = tid; s < 8*68; s += 256) sm.t.wrs[40*68 + s] = 0u;

    float acc[3][4][4];
#pragma unroll
    for (int mt = 0; mt < 3; mt++)
#pragma unroll
        for (int nt = 0; nt < 4; nt++)
#pragma unroll
            for (int q = 0; q < 4; q++) acc[mt][nt][q] = 0.0f;

    const float4* wr4 = (const float4*)wr;
    float4 wbuf[5];
    uint4  xbuf[2];

    /* prefetch tile 0 */
    {
        int k0 = chunk*FC_KC;
#pragma unroll
        for (int s = 0; s < 5; s++) {
            int idx = tid + s*256;
            int r = idx >> 5, cc = idx & 31;
            wbuf[s] = wr4[(size_t)r*(K_FC/4) + (k0 >> 2) + cc];
        }
#pragma unroll
        for (int s = 0; s < 2; s++) {
            int idx = tid + s*256;
            int r = idx >> 4, cc = idx & 15;
            xbuf[s] = *(const uint4*)(g_x1h + (size_t)r*K_FC + k0 + cc*8);
        }
    }

    for (int tile = 0; tile < FC_TILES; tile++) {
        /* commit prefetched tile to smem */
#pragma unroll
        for (int s = 0; s < 5; s++) {
            int idx = tid + s*256;
            int r = idx >> 5, cc = idx & 31;
            sm.t.wrs[r*68 + 2*cc]     = packbf2(wbuf[s].x, wbuf[s].y);
            sm.t.wrs[r*68 + 2*cc + 1] = packbf2(wbuf[s].z, wbuf[s].w);
        }
#pragma unroll
        for (int s = 0; s < 2; s++) {
            int idx = tid + s*256;
            int r = idx >> 4, cc = idx & 15;
            *(uint4*)&sm.t.x1s[r*68 + cc*4] = xbuf[s];
        }
        __syncthreads();

        /* prefetch next tile while computing this one */
        if (tile + 1 < FC_TILES) {
            int k0 = chunk*FC_KC + (tile+1)*128;
#pragma unroll
            for (int s = 0; s < 5; s++) {
                int idx = tid + s*256;
                int r = idx >> 5, cc = idx & 31;
                wbuf[s] = wr4[(size_t)r*(K_FC/4) + (k0 >> 2) + cc];
            }
#pragma unroll
            for (int s = 0; s < 2; s++) {
                int idx = tid + s*256;
                int r = idx >> 4, cc = idx & 15;
                xbuf[s] = *(const uint4*)(g_x1h + (size_t)r*K_FC + k0 + cc*8);
            }
        }

        int ko = warp*8 + tig;
        uint32_t bfrag[4][2];
#pragma unroll
        for (int nt = 0; nt < 4; nt++) {
            bfrag[nt][0] = sm.t.x1s[(nt*8 + gid)*68 + ko];
            bfrag[nt][1] = sm.t.x1s[(nt*8 + gid)*68 + ko + 4];
        }
#pragma unroll
        for (int mt = 0; mt < 3; mt++) {
            uint32_t afrag[4];
            afrag[0] = sm.t.wrs[(mt*16 + gid    )*68 + ko];
            afrag[1] = sm.t.wrs[(mt*16 + gid + 8)*68 + ko];
            afrag[2] = sm.t.wrs[(mt*16 + gid    )*68 + ko + 4];
            afrag[3] = sm.t.wrs[(mt*16 + gid + 8)*68 + ko + 4];
#pragma unroll
            for (int nt = 0; nt < 4; nt++)
                mma_bf16(acc[mt][nt], afrag, bfrag[nt]);
        }
        __syncthreads();
    }

    /* per-warp results -> red[warp][f*32+b]; rows f>=40 dropped */
#pragma unroll
    for (int mt = 0; mt < 3; mt++)
#pragma unroll
        for (int nt = 0; nt < 4; nt++) {
            int f0 = mt*16 + gid;
            int b0 = nt*8 + 2*tig;
            float* rp = sm.red + warp*(FREQ*BB);
            if (f0 < FREQ) {
                rp[f0*BB + b0]     = acc[mt][nt][0];
                rp[f0*BB + b0 + 1] = acc[mt][nt][1];
            }
            if (f0 + 8 < FREQ) {
                rp[(f0+8)*BB + b0]     = acc[mt][nt][2];
                rp[(f0+8)*BB + b0 + 1] = acc[mt][nt][3];
            }
        }
    __syncthreads();
    /* transposed partial store: g_gpart[p][chunk] for coalesced gate reads */
    for (int p = tid; p < FREQ*BB; p += 256) {
        float s = 0.0f;
#pragma unroll
        for (int w = 0; w < 8; w++) s += sm.red[w*(FREQ*BB) + p];
        g_gpart[(size_t)p*NCHUNK + chunk] = s;
    }
}

/* ---------------- gate: warp-per-p coalesced reduce + sigmoid ------------ */
__global__ void gate_kernel(const float* __restrict__ br) {
    int warp = threadIdx.x >> 5;
    int lane = threadIdx.x & 31;
    int p = blockIdx.x*8 + warp;           /* grid 160, p = f*32 + b */
    const float* gp = g_gpart + (size_t)p*NCHUNK;
    float s = 0.0f;
    for (int c = lane; c < NCHUNK; c += 32) s += gp[c];
#pragma unroll
    for (int o = 16; o > 0; o >>= 1)
        s += __shfl_xor_sync(0xffffffffu, s, o);
    if (lane == 0) {
        int f = p >> 5;
        int b = p & 31;
        s += __ldg(&br[f]);
        g_gates[b*FREQ + f] = 1.0f / (1.0f + expf(-s));
    }
}

/* ---------------- weighted mean of gates --------------------------------- */
__global__ void wtd_kernel(float* __restrict__ out, int out_size) {
    __shared__ float red[256];
    int tid = threadIdx.x;
    float s = 0.0f;
    for (int i = tid; i < BB*FREQ; i += 256) {
        int f = i % FREQ;
        s += g_gates[i] * (2.0f * (float)(f+1));
    }
    red[tid] = s;
    __syncthreads();
    for (int o = 128; o > 0; o >>= 1) {
        if (tid < o) red[tid] += red[tid + o];
        __syncthreads();
    }
    if (tid == 0) out[out_size - 1] = red[0] / (float)(BB*FREQ);
}

/* ---------------- projection (trig fused): grid (b, f), 128 thr ---------- */
__global__ void proj_kernel(float* __restrict__ out) {
    __shared__ float sp[WW];
    __shared__ float cp[WW];
    int b = blockIdx.x;
    int f = blockIdx.y;
    int tid  = threadIdx.x;
    int warp = tid >> 5;
    int lane = tid & 31;

    float fs = 2.0f * (float)(f+1);
#pragma unroll
    for (int q = 0; q < 2; q++) {
        int w = tid + q*128;
        float t  = (0.5f/255.0f) * (float)w;
        float ph = TWO_PI * fs * t;
        float sv, cv;
        sincosf(ph, &sv, &cv);
        sp[w] = sv;
        cp[w] = cv;
    }
    __syncthreads();

    float gate = g_gates[b*FREQ + f];
    for (int h = warp; h < HH; h += 4) {
        const float* xp = g_feats + ((size_t)b*HH + h)*WW;
        float s = 0.0f, c = 0.0f;
#pragma unroll
        for (int q = 0; q < 8; q++) {
            int w = lane + q*32;
            float v = xp[w];
            s += sp[w]*v;
            c += cp[w]*v;
        }
#pragma unroll
        for (int o = 16; o > 0; o >>= 1) {
            s += __shfl_xor_sync(0xffffffffu, s, o);
            c += __shfl_xor_sync(0xffffffffu, c, o);
        }
        if (lane == 0) {
            s *= (1.0f/(float)WW);
            c *= (1.0f/(float)WW);
            out[(size_t)b*(FREQ*HH) + f*HH + h] = sqrtf(s*s + c*c) * gate;
        }
    }
}

/* ---------------- launch -------------------------------------------------- */
extern "C" void kernel_launch(void* const* d_in, const int* in_sizes, int n_in,
                              void* d_out, int out_size) {
    const float* in = (const float*)d_in[0];
    const float* w0 = (const float*)d_in[1];
    const float* b0 = (const float*)d_in[2];
    const float* w1 = (const float*)d_in[3];
    const float* b1 = (const float*)d_in[4];
    const float* wf = (const float*)d_in[5];
    const float* bf = (const float*)d_in[6];
    const float* wr = (const float*)d_in[7];
    const float* br = (const float*)d_in[8];
    float* out = (float*)d_out;

    cudaFuncSetAttribute(conv1_mma_kernel,
                         cudaFuncAttributeMaxDynamicSharedMemorySize, SM1);

    prep_kernel<<<6162, 256>>>(in, w0, b0, wf, bf, w1);
    conv1_mma_kernel<<<dim3(18, BB), 1024, SM1>>>(b1);
    fc_kernel<<<NCHUNK, 256>>>(wr);
    gate_kernel<<<160, 256>>>(br);
    wtd_kernel<<<1, 256>>>(out, out_size);
    proj_kernel<<<dim3(BB, FREQ), 128>>>(out);
}

// round 9
// speedup vs baseline: 5.1206x; 1.3810x over previous
#include <cuda_runtime.h>
#include <cuda_bf16.h>
#include <math.h>
#include <stdint.h>

#define BB   32
#define HH   40
#define WW   256
#define FREQ 40
#define C0   32
#define H0   38
#define C1   64
#define H1   36
#define W1   252
#define K_FC (C1*H1*W1)          /* 580608 */
#define FC_TILES 12
#define FC_KC (FC_TILES*128)     /* 1536 */
#define NCHUNK 378               /* K_FC / FC_KC */
#define TWO_PI 6.28318530717958647692f

/* ---------------- scratch (device globals) ------------------------------- */
/* x0 packed: [b][icp(16)][i(38)][j(256)] u32 = bf16x2 (ic even lo, odd hi) */
__device__ uint32_t      g_x0p[(size_t)BB*16*H0*256];
__device__ __nv_bfloat16 g_x1h[(size_t)BB*K_FC];      /* conv1 out, bf16   */
__device__ uint4         g_wfragq[9*2*4*32];          /* w1 bf16 frag order */
__device__ float         g_feats[BB*HH*WW];
__device__ float         g_sin[FREQ*WW];
__device__ float         g_cos[FREQ*WW];
__device__ float         g_gpart[(size_t)FREQ*BB*NCHUNK];  /* [p][chunk] */
__device__ float         g_gates[BB*FREQ];

/* ---------------- helpers ------------------------------------------------- */
__device__ __forceinline__ uint32_t packbf2(float lo, float hi) {
    __nv_bfloat162 h = __floats2bfloat162_rn(lo, hi);
    return *(uint32_t*)&h;
}

__device__ __forceinline__ void mma_bf16(float c[4], const uint32_t a[4],
                                         const uint32_t b[2]) {
    asm volatile(
        "mma.sync.aligned.m16n8k16.row.col.f32.bf16.bf16.f32 "
        "{%0,%1,%2,%3}, {%4,%5,%6,%7}, {%8,%9}, {%0,%1,%2,%3};"
        : "+f"(c[0]), "+f"(c[1]), "+f"(c[2]), "+f"(c[3])
        : "r"(a[0]), "r"(a[1]), "r"(a[2]), "r"(a[3]), "r"(b[0]), "r"(b[1]));
}

/* ---------------- fused prep: conv0 + feats + wprep + trig ---------------
 * blocks [0,4864): conv0; [4864,6144): feats; [6144,6153): wprep;
 * [6153,6193): trig */
__global__ void prep_kernel(const float* __restrict__ in,
                            const float* __restrict__ w0,
                            const float* __restrict__ b0,
                            const float* __restrict__ wf,
                            const float* __restrict__ bf,
                            const float* __restrict__ w1) {
    int bid = blockIdx.x;
    if (bid < 4864) {
        /* conv0: 1->32ch 3x3 VALID + bias + relu, bf16x2-packed output */
        int idx = bid*256 + threadIdx.x;
        int jg = idx & 63;
        int t  = idx >> 6;
        int i  = t % H0;  t /= H0;
        int op = t % 16;  t /= 16;
        int b  = t;
        int j0 = jg*4;
        int oc0 = op*2;

        float wA[9], wB[9];
#pragma unroll
        for (int q = 0; q < 9; q++) {
            wA[q] = __ldg(&w0[oc0*9+q]);
            wB[q] = __ldg(&w0[(oc0+1)*9+q]);
        }
        float biasA = __ldg(&b0[oc0]);
        float biasB = __ldg(&b0[oc0+1]);
        float aA[4] = {biasA, biasA, biasA, biasA};
        float aB[4] = {biasB, biasB, biasB, biasB};

        const float* ip = in + (size_t)b*HH*WW;
#pragma unroll
        for (int di = 0; di < 3; di++) {
            const float* row = ip + (i+di)*WW;
            float x[6];
#pragma unroll
            for (int c = 0; c < 6; c++) x[c] = (j0+c < WW) ? row[j0+c] : 0.0f;
#pragma unroll
            for (int dj = 0; dj < 3; dj++) {
                float wa = wA[di*3+dj], wb = wB[di*3+dj];
#pragma unroll
                for (int q = 0; q < 4; q++) {
                    aA[q] += wa * x[q+dj];
                    aB[q] += wb * x[q+dj];
                }
            }
        }
        uint4 v;
        uint32_t* vp = &v.x;
#pragma unroll
        for (int q = 0; q < 4; q++) {
            bool ok = (j0+q < 254);
            vp[q] = packbf2(ok ? fmaxf(aA[q], 0.0f) : 0.0f,
                            ok ? fmaxf(aB[q], 0.0f) : 0.0f);
        }
        *(uint4*)(g_x0p + (((size_t)b*16 + op)*H0 + i)*256 + j0) = v;
    } else if (bid < 6144) {
        /* feats: 5-tap conv along W, zero pad, + bias */
        int idx = (bid - 4864)*256 + threadIdx.x;
        int w = idx & (WW-1);
        const float* row = in + (idx - w);
        float acc = __ldg(&bf[0]);
#pragma unroll
        for (int t = 0; t < 5; t++) {
            int ww = w + t - 2;
            if (ww >= 0 && ww < WW) acc += __ldg(&wf[t]) * row[ww];
        }
        g_feats[idx] = acc;
    } else if (bid < 6153) {
        /* wprep: w1 -> bf16 uint4 frag layout [t9][kh][nq][lane] */
        int t = (bid - 6144)*256 + threadIdx.x;   /* 0..2303 */
        int lane = t & 31;
        int nq   = (t >> 5) & 3;
        int kh   = (t >> 7) & 1;
        int t9   = t >> 8;
        int gid = lane >> 2, tig = lane & 3;
        int ic0 = 2*tig + 16*kh;
        int oc0 = nq*16 + gid;        /* nf = 0 */
        int oc1 = oc0 + 8;            /* nf = 1 */
        uint4 v;
        v.x = packbf2(__ldg(&w1[oc0*288 + (ic0  )*9 + t9]),
                      __ldg(&w1[oc0*288 + (ic0+1)*9 + t9]));
        v.y = packbf2(__ldg(&w1[oc0*288 + (ic0+8)*9 + t9]),
                      __ldg(&w1[oc0*288 + (ic0+9)*9 + t9]));
        v.z = packbf2(__ldg(&w1[oc1*288 + (ic0  )*9 + t9]),
                      __ldg(&w1[oc1*288 + (ic0+1)*9 + t9]));
        v.w = packbf2(__ldg(&w1[oc1*288 + (ic0+8)*9 + t9]),
                      __ldg(&w1[oc1*288 + (ic0+9)*9 + t9]));
        g_wfragq[((t9*2 + kh)*4 + nq)*32 + lane] = v;
    } else {
        /* trig tables */
        int f = bid - 6153;
        int w = threadIdx.x;
        float fs = 2.0f * (float)(f+1);
        float t  = (0.5f/255.0f) * (float)w;
        float ph = TWO_PI * fs * t;
        float sv, cv;
        sincosf(ph, &sv, &cv);
        g_sin[f*WW + w] = sv;
        g_cos[f*WW + w] = cv;
    }
}

/* ---------------- conv1 via bf16 m16n8k16, 2 output rows per CTA --------- */
#define XR    258
#define SM1   (64*XR*4)          /* 66048 bytes */

__global__ void __launch_bounds__(1024, 1)
conv1_mma_kernel(const float* __restrict__ b1) {
    extern __shared__ uint32_t xsp[];

    int i2  = blockIdx.x;
    int b   = blockIdx.y;
    int tid = threadIdx.x;

    /* stage 4 input rows x 16 icp (uint2 = 8B, rows 2*i2 .. 2*i2+3) */
    for (int t = tid; t < 64*128; t += 1024) {
        int c2 = t & 127;
        int r  = t >> 7;            /* r = icp*4 + dr */
        int dr = r & 3;
        int ic = r >> 2;
        uint2 v = *(const uint2*)(g_x0p +
            (((size_t)b*16 + ic)*H0 + (2*i2 + dr))*256 + c2*2);
        *(uint2*)(xsp + r*XR + c2*2) = v;
    }
    if (tid < 128) xsp[(tid >> 1)*XR + 256 + (tid & 1)] = 0u;
    __syncthreads();

    int warp = tid >> 5;
    int lane = tid & 31;
    int nq   = warp & 3;
    int mblk = (warp >> 2) & 3;
    int rsel = warp >> 4;
    int gid  = lane >> 2;
    int tig  = lane & 3;

    float cacc[4][2][4];
#pragma unroll
    for (int mf = 0; mf < 4; mf++)
#pragma unroll
        for (int nf = 0; nf < 2; nf++)
#pragma unroll
            for (int q = 0; q < 4; q++) cacc[mf][nf][q] = 0.0f;

#pragma unroll
    for (int t9 = 0; t9 < 9; t9++) {
        int di = t9 / 3, dj = t9 % 3;
        int dr = di + rsel;
#pragma unroll
        for (int kh = 0; kh < 2; kh++) {
            uint4 wv = __ldg(&g_wfragq[((t9*2 + kh)*4 + nq)*32 + lane]);
            uint32_t bfrag[2][2];
            bfrag[0][0] = wv.x; bfrag[0][1] = wv.y;
            bfrag[1][0] = wv.z; bfrag[1][1] = wv.w;
            const uint32_t* xa = xsp + ((kh*8 + tig    )*4 + dr)*XR + dj;
            const uint32_t* xb = xsp + ((kh*8 + tig + 4)*4 + dr)*XR + dj;
#pragma unroll
            for (int mf = 0; mf < 4; mf++) {
                int j0 = mblk*64 + mf*16 + gid;
                uint32_t afrag[4];
                afrag[0] = xa[j0];
                afrag[1] = xa[j0 + 8];
                afrag[2] = xb[j0];
                afrag[3] = xb[j0 + 8];
                mma_bf16(cacc[mf][0], afrag, bfrag[0]);
                mma_bf16(cacc[mf][1], afrag, bfrag[1]);
            }
        }
    }

    /* epilogue: bias + relu + bf16 store to g_x1h[b][oc][i][j] */
    int i = 2*i2 + rsel;
#pragma unroll
    for (int nf = 0; nf < 2; nf++) {
        int oc = nq*16 + nf*8 + tig*2;
        float bias0 = __ldg(&b1[oc]);
        float bias1 = __ldg(&b1[oc+1]);
        __nv_bfloat16* o0 = g_x1h + (size_t)b*K_FC + (size_t)oc*(H1*W1) + (size_t)i*W1;
        __nv_bfloat16* o1 = o0 + H1*W1;
#pragma unroll
        for (int mf = 0; mf < 4; mf++) {
            int j = mblk*64 + mf*16 + gid;
            if (j < W1) {
                o0[j] = __float2bfloat16_rn(fmaxf(cacc[mf][nf][0] + bias0, 0.0f));
                o1[j] = __float2bfloat16_rn(fmaxf(cacc[mf][nf][1] + bias1, 0.0f));
            }
            if (j + 8 < W1) {
                o0[j+8] = __float2bfloat16_rn(fmaxf(cacc[mf][nf][2] + bias0, 0.0f));
                o1[j+8] = __float2bfloat16_rn(fmaxf(cacc[mf][nf][3] + bias1, 0.0f));
            }
        }
    }
}

/* ---------------- FC via bf16 tensor cores, register double-buffered -----
 * 378 blocks x 12 k128-tiles. */
__global__ void __launch_bounds__(256) fc_kernel(const float* __restrict__ wr) {
    __shared__ union {
        struct { uint32_t wrs[48*68]; uint32_t x1s[32*68]; } t;
        float red[8*FREQ*BB];
    } sm;
    int chunk = blockIdx.x;
    int tid   = threadIdx.x;
    int warp  = tid >> 5;
    int lane  = tid & 31;
    int gid   = lane >> 2;
    int tig   = lane & 3;

    /* wrs rows 40..47 stay zero for all tiles */
    for (int s = tid; s < 8*68; s += 256) sm.t.wrs[40*68 + s] = 0u;

    float acc[3][4][4];
#pragma unroll
    for (int mt = 0; mt < 3; mt++)
#pragma unroll
        for (int nt = 0; nt < 4; nt++)
#pragma unroll
            for (int q = 0; q < 4; q++) acc[mt][nt][q] = 0.0f;

    const float4* wr4 = (const float4*)wr;
    float4 wbuf[5];
    uint4  xbuf[2];

    /* prefetch tile 0 */
    {
        int k0 = chunk*FC_KC;
#pragma unroll
        for (int s = 0; s < 5; s++) {
            int idx = tid + s*256;
            int r = idx >> 5, cc = idx & 31;
            wbuf[s] = wr4[(size_t)r*(K_FC/4) + (k0 >> 2) + cc];
        }
#pragma unroll
        for (int s = 0; s < 2; s++) {
            int idx = tid + s*256;
            int r = idx >> 4, cc = idx & 15;
            xbuf[s] = *(const uint4*)(g_x1h + (size_t)r*K_FC + k0 + cc*8);
        }
    }

    for (int tile = 0; tile < FC_TILES; tile++) {
        /* commit prefetched tile to smem */
#pragma unroll
        for (int s = 0; s < 5; s++) {
            int idx = tid + s*256;
            int r = idx >> 5, cc = idx & 31;
            sm.t.wrs[r*68 + 2*cc]     = packbf2(wbuf[s].x, wbuf[s].y);
            sm.t.wrs[r*68 + 2*cc + 1] = packbf2(wbuf[s].z, wbuf[s].w);
        }
#pragma unroll
        for (int s = 0; s < 2; s++) {
            int idx = tid + s*256;
            int r = idx >> 4, cc = idx & 15;
            *(uint4*)&sm.t.x1s[r*68 + cc*4] = xbuf[s];
        }
        __syncthreads();

        /* prefetch next tile while computing this one */
        if (tile + 1 < FC_TILES) {
            int k0 = chunk*FC_KC + (tile+1)*128;
#pragma unroll
            for (int s = 0; s < 5; s++) {
                int idx = tid + s*256;
                int r = idx >> 5, cc = idx & 31;
                wbuf[s] = wr4[(size_t)r*(K_FC/4) + (k0 >> 2) + cc];
            }
#pragma unroll
            for (int s = 0; s < 2; s++) {
                int idx = tid + s*256;
                int r = idx >> 4, cc = idx & 15;
                xbuf[s] = *(const uint4*)(g_x1h + (size_t)r*K_FC + k0 + cc*8);
            }
        }

        int ko = warp*8 + tig;
        uint32_t bfrag[4][2];
#pragma unroll
        for (int nt = 0; nt < 4; nt++) {
            bfrag[nt][0] = sm.t.x1s[(nt*8 + gid)*68 + ko];
            bfrag[nt][1] = sm.t.x1s[(nt*8 + gid)*68 + ko + 4];
        }
#pragma unroll
        for (int mt = 0; mt < 3; mt++) {
            uint32_t afrag[4];
            afrag[0] = sm.t.wrs[(mt*16 + gid    )*68 + ko];
            afrag[1] = sm.t.wrs[(mt*16 + gid + 8)*68 + ko];
            afrag[2] = sm.t.wrs[(mt*16 + gid    )*68 + ko + 4];
            afrag[3] = sm.t.wrs[(mt*16 + gid + 8)*68 + ko + 4];
#pragma unroll
            for (int nt = 0; nt < 4; nt++)
                mma_bf16(acc[mt][nt], afrag, bfrag[nt]);
        }
        __syncthreads();
    }

    /* per-warp results -> red[warp][f*32+b]; rows f>=40 dropped */
#pragma unroll
    for (int mt = 0; mt < 3; mt++)
#pragma unroll
        for (int nt = 0; nt < 4; nt++) {
            int f0 = mt*16 + gid;
            int b0 = nt*8 + 2*tig;
            float* rp = sm.red + warp*(FREQ*BB);
            if (f0 < FREQ) {
                rp[f0*BB + b0]     = acc[mt][nt][0];
                rp[f0*BB + b0 + 1] = acc[mt][nt][1];
            }
            if (f0 + 8 < FREQ) {
                rp[(f0+8)*BB + b0]     = acc[mt][nt][2];
                rp[(f0+8)*BB + b0 + 1] = acc[mt][nt][3];
            }
        }
    __syncthreads();
    /* transposed partial store: g_gpart[p][chunk] for coalesced gate reads */
    for (int p = tid; p < FREQ*BB; p += 256) {
        float s = 0.0f;
#pragma unroll
        for (int w = 0; w < 8; w++) s += sm.red[w*(FREQ*BB) + p];
        g_gpart[(size_t)p*NCHUNK + chunk] = s;
    }
}

/* ---------------- gate: warp-per-p coalesced reduce + sigmoid ------------ */
__global__ void gate_kernel(const float* __restrict__ br) {
    int warp = threadIdx.x >> 5;
    int lane = threadIdx.x & 31;
    int p = blockIdx.x*8 + warp;           /* grid 160, p = f*32 + b */
    const float* gp = g_gpart + (size_t)p*NCHUNK;
    float s = 0.0f;
    for (int c = lane; c < NCHUNK; c += 32) s += gp[c];
#pragma unroll
    for (int o = 16; o > 0; o >>= 1)
        s += __shfl_xor_sync(0xffffffffu, s, o);
    if (lane == 0) {
        int f = p >> 5;
        int b = p & 31;
        s += __ldg(&br[f]);
        g_gates[b*FREQ + f] = 1.0f / (1.0f + expf(-s));
    }
}

/* ---------------- weighted mean of gates --------------------------------- */
__global__ void wtd_kernel(float* __restrict__ out, int out_size) {
    __shared__ float red[256];
    int tid = threadIdx.x;
    float s = 0.0f;
    for (int i = tid; i < BB*FREQ; i += 256) {
        int f = i % FREQ;
        s += g_gates[i] * (2.0f * (float)(f+1));
    }
    red[tid] = s;
    __syncthreads();
    for (int o = 128; o > 0; o >>= 1) {
        if (tid < o) red[tid] += red[tid + o];
        __syncthreads();
    }
    if (tid == 0) out[out_size - 1] = red[0] / (float)(BB*FREQ);
}

/* ---------------- projection: warp-per-dot, trig tables, grid (b, f) ----- */
__global__ void proj_kernel(float* __restrict__ out) {
    int b = blockIdx.x;
    int f = blockIdx.y;
    int warp = threadIdx.x >> 5;
    int lane = threadIdx.x & 31;
    const float* sp = g_sin + f*WW;
    const float* cp = g_cos + f*WW;
    float gate = g_gates[b*FREQ + f];
    for (int h = warp; h < HH; h += 4) {
        const float* xp = g_feats + ((size_t)b*HH + h)*WW;
        float s = 0.0f, c = 0.0f;
#pragma unroll
        for (int q = 0; q < 8; q++) {
            int w = lane + q*32;
            float v = xp[w];
            s += sp[w]*v;
            c += cp[w]*v;
        }
#pragma unroll
        for (int o = 16; o > 0; o >>= 1) {
            s += __shfl_xor_sync(0xffffffffu, s, o);
            c += __shfl_xor_sync(0xffffffffu, c, o);
        }
        if (lane == 0) {
            s *= (1.0f/(float)WW);
            c *= (1.0f/(float)WW);
            out[(size_t)b*(FREQ*HH) + f*HH + h] = sqrtf(s*s + c*c) * gate;
        }
    }
}

/* ---------------- launch -------------------------------------------------- */
extern "C" void kernel_launch(void* const* d_in, const int* in_sizes, int n_in,
                              void* d_out, int out_size) {
    const float* in = (const float*)d_in[0];
    const float* w0 = (const float*)d_in[1];
    const float* b0 = (const float*)d_in[2];
    const float* w1 = (const float*)d_in[3];
    const float* b1 = (const float*)d_in[4];
    const float* wf = (const float*)d_in[5];
    const float* bf = (const float*)d_in[6];
    const float* wr = (const float*)d_in[7];
    const float* br = (const float*)d_in[8];
    float* out = (float*)d_out;

    cudaFuncSetAttribute(conv1_mma_kernel,
                         cudaFuncAttributeMaxDynamicSharedMemorySize, SM1);

    prep_kernel<<<6193, 256>>>(in, w0, b0, wf, bf, w1);
    conv1_mma_kernel<<<dim3(18, BB), 1024, SM1>>>(b1);
    fc_kernel<<<NCHUNK, 256>>>(wr);
    gate_kernel<<<160, 256>>>(br);
    wtd_kernel<<<1, 256>>>(out, out_size);
    proj_kernel<<<dim3(BB, FREQ), 128>>>(out);
}